// round 3
// baseline (speedup 1.0000x reference)
#include <cuda_runtime.h>
#include <math.h>

// Problem constants
#define B_   64
#define S_   128
#define T_   10
#define E_   300
#define D_   100
#define H_   256
#define IN_  500
#define KP_  512          // padded K for the big GEMM
#define G4_  1024         // 4*H
#define NTOK (B_*S_)      // 8192

// ---------------- scratch (static device globals; no runtime alloc) ----------
__device__ float g_WihT[KP_*G4_];          // [512][1024]  (zero-padded rows >= 500)
__device__ float g_WhhT[H_*G4_];           // [256][1024]
__device__ float g_tin[(size_t)NTOK*KP_];  // [8192][512]  (cols 500..511 zero)
__device__ float g_xg[(size_t)NTOK*G4_];   // [8192][1024]
__device__ float g_hout[(size_t)NTOK*H_];  // [64][128][256]

__device__ __forceinline__ float sigmf(float x) { return 1.f/(1.f+expf(-x)); }

// ---------------- prep: transpose W_ih (pad K to 512) and W_hh ---------------
__global__ void prep_kernel(const float* __restrict__ W_ih,
                            const float* __restrict__ W_hh) {
  int idx = blockIdx.x*256 + threadIdx.x;
  if (idx < KP_*G4_) {
    int k = idx >> 10, o = idx & 1023;
    g_WihT[idx] = (k < IN_) ? W_ih[o*IN_ + k] : 0.f;
  }
  if (idx < H_*G4_) {
    int k = idx >> 10, o = idx & 1023;
    g_WhhT[idx] = W_hh[o*H_ + k];
  }
}

// ---------------- K1: graph attention + t_in assembly ------------------------
#define TOKB 8
#define WTS  101   // padded stride for W_ent^T in smem (conflict-free)

__global__ void graph_tin_kernel(const int* __restrict__ inputs,
                                 const int* __restrict__ triples,
                                 const int* __restrict__ id2,
                                 const float* __restrict__ emb,
                                 const float* __restrict__ ent,
                                 const float* __restrict__ rel,
                                 const float* __restrict__ W_ent) {
  extern __shared__ float sm[];
  float* Wt = sm;                   // [200][101]  Wt[k*101+d] = W_ent[d][k]
  float* ht = Wt + 200*WTS;         // [10][200]
  float* er = ht + T_*200;          // [10][100]
  __shared__ float ev[T_];
  __shared__ float alpha[T_];
  __shared__ int   s_valid;
  int tid = threadIdx.x;            // 256 threads

  // load transposed W_ent into smem (stride 101 -> conflict-free stores/loads)
  for (int idx = tid; idx < D_*2*D_; idx += 256) {
    int d = idx / 200, k = idx % 200;
    Wt[k*WTS + d] = W_ent[idx];
  }
  __syncthreads();

  for (int tt = 0; tt < TOKB; tt++) {
    int tok = blockIdx.x*TOKB + tt;
    const int* tri = triples + tok*T_*3;

    // gather ht = [eh || et], er
    for (int idx = tid; idx < T_*200; idx += 256) {
      int t = idx / 200, j = idx % 200;
      int r  = (j < D_) ? tri[t*3] : tri[t*3+1];
      int jj = (j < D_) ? j : j - D_;
      ht[idx] = ent[(size_t)r*D_ + jj];
    }
    for (int idx = tid; idx < T_*D_; idx += 256) {
      int t = idx / D_, j = idx % D_;
      er[idx] = rel[(size_t)tri[t*3+2]*D_ + j];
    }
    if (tid < T_) ev[tid] = 0.f;
    if (tid == 0) {
      int v = 0;
      for (int t = 0; t < T_; t++) v |= (id2[tok*T_+t] != -1);
      s_valid = v;
    }
    __syncthreads();

    // e[t] = sum_d tanh(Wt[:,d] . ht[t]) * er[t][d]
    // thread = (tg, d); tg in {0,1} -> 5 triples each (weight reuse x5)
    if (tid < 200) {
      int d  = tid % D_;
      int tg = tid / D_;
      const float* h0 = ht + (tg*5+0)*200;
      const float* h1 = ht + (tg*5+1)*200;
      const float* h2 = ht + (tg*5+2)*200;
      const float* h3 = ht + (tg*5+3)*200;
      const float* h4 = ht + (tg*5+4)*200;
      float a0=0.f,a1=0.f,a2=0.f,a3=0.f,a4=0.f;
      for (int k = 0; k < 200; k += 4) {
        float4 v0 = *(const float4*)(h0+k);
        float4 v1 = *(const float4*)(h1+k);
        float4 v2 = *(const float4*)(h2+k);
        float4 v3 = *(const float4*)(h3+k);
        float4 v4 = *(const float4*)(h4+k);
        float w0 = Wt[(k+0)*WTS+d];
        float w1 = Wt[(k+1)*WTS+d];
        float w2 = Wt[(k+2)*WTS+d];
        float w3 = Wt[(k+3)*WTS+d];
        a0 += w0*v0.x + w1*v0.y + w2*v0.z + w3*v0.w;
        a1 += w0*v1.x + w1*v1.y + w2*v1.z + w3*v1.w;
        a2 += w0*v2.x + w1*v2.y + w2*v2.z + w3*v2.w;
        a3 += w0*v3.x + w1*v3.y + w2*v3.z + w3*v3.w;
        a4 += w0*v4.x + w1*v4.y + w2*v4.z + w3*v4.w;
      }
      atomicAdd(&ev[tg*5+0], tanhf(a0)*er[(tg*5+0)*D_+d]);
      atomicAdd(&ev[tg*5+1], tanhf(a1)*er[(tg*5+1)*D_+d]);
      atomicAdd(&ev[tg*5+2], tanhf(a2)*er[(tg*5+2)*D_+d]);
      atomicAdd(&ev[tg*5+3], tanhf(a3)*er[(tg*5+3)*D_+d]);
      atomicAdd(&ev[tg*5+4], tanhf(a4)*er[(tg*5+4)*D_+d]);
    }
    __syncthreads();

    if (tid == 0) {  // softmax over 10 triples
      float mx = ev[0];
      for (int t = 1; t < T_; t++) mx = fmaxf(mx, ev[t]);
      float sum = 0.f;
      for (int t = 0; t < T_; t++) { float e = expf(ev[t]-mx); alpha[t]=e; sum+=e; }
      float inv = 1.f/sum;
      for (int t = 0; t < T_; t++) alpha[t] *= inv;
    }
    __syncthreads();

    // write t_in row: [x(300) | graph(200) | pad(12)=0]
    float* row = g_tin + (size_t)tok*KP_;
    const float* xr = emb + (size_t)inputs[tok]*E_;
    for (int j = tid; j < E_; j += 256) row[j] = xr[j];
    float vm = s_valid ? 1.f : 0.f;
    for (int j = tid; j < 200; j += 256) {
      float g = 0.f;
      #pragma unroll
      for (int t = 0; t < T_; t++) g += alpha[t]*ht[t*200+j];
      row[E_+j] = g*vm;
    }
    if (tid < KP_-IN_) row[IN_+tid] = 0.f;
    __syncthreads();  // protect ht before next token overwrites it
  }
}

// ---------------- K2: xg = t_in @ W_ih^T + b  (SGEMM 8192x1024x512) ----------
#define BM 64
#define BN 64
#define BK 16

__global__ __launch_bounds__(256) void gemm_xg_kernel(const float* __restrict__ bias) {
  __shared__ float As[BK][BM+4];
  __shared__ float Bs[BK][BN];
  int tid = threadIdx.x;
  int tx = tid & 15, ty = tid >> 4;
  int bm = blockIdx.y * BM, bn = blockIdx.x * BN;
  int arow = tid >> 2, acol = (tid & 3) << 2;
  int brow = tid >> 4, bcol = (tid & 15) << 2;
  const float* Ab = g_tin + (size_t)bm*KP_;
  float acc[4][4] = {};
  for (int k0 = 0; k0 < KP_; k0 += BK) {
    float4 av = *(const float4*)&Ab[(size_t)arow*KP_ + k0 + acol];
    As[acol+0][arow]=av.x; As[acol+1][arow]=av.y;
    As[acol+2][arow]=av.z; As[acol+3][arow]=av.w;
    *(float4*)&Bs[brow][bcol] = *(const float4*)&g_WihT[(size_t)(k0+brow)*G4_ + bn + bcol];
    __syncthreads();
    #pragma unroll
    for (int k = 0; k < BK; k++) {
      float a0 = As[k][ty*4+0], a1 = As[k][ty*4+1];
      float a2 = As[k][ty*4+2], a3 = As[k][ty*4+3];
      float b0 = Bs[k][tx*4+0], b1 = Bs[k][tx*4+1];
      float b2 = Bs[k][tx*4+2], b3 = Bs[k][tx*4+3];
      acc[0][0]+=a0*b0; acc[0][1]+=a0*b1; acc[0][2]+=a0*b2; acc[0][3]+=a0*b3;
      acc[1][0]+=a1*b0; acc[1][1]+=a1*b1; acc[1][2]+=a1*b2; acc[1][3]+=a1*b3;
      acc[2][0]+=a2*b0; acc[2][1]+=a2*b1; acc[2][2]+=a2*b2; acc[2][3]+=a2*b3;
      acc[3][0]+=a3*b0; acc[3][1]+=a3*b1; acc[3][2]+=a3*b2; acc[3][3]+=a3*b3;
    }
    __syncthreads();
  }
  #pragma unroll
  for (int i = 0; i < 4; i++) {
    int r = bm + ty*4 + i;
    int cc = bn + tx*4;
    float4 o;
    o.x = acc[i][0] + bias[cc+0];
    o.y = acc[i][1] + bias[cc+1];
    o.z = acc[i][2] + bias[cc+2];
    o.w = acc[i][3] + bias[cc+3];
    *(float4*)&g_xg[(size_t)r*G4_ + cc] = o;
  }
}

// ---------------- K3: LSTM scan + masked attention pooling + logits ----------
// 32 blocks x 512 threads; each block owns 2 batches (W_hh load reused x2).
__global__ __launch_bounds__(512) void lstm_attend_kernel(
    const int*   __restrict__ lengths,
    const float* __restrict__ attn_w,
    const float* __restrict__ attn_b,
    const float* __restrict__ out_w,
    const float* __restrict__ out_b,
    float*       __restrict__ out) {
  __shared__ float h0s[H_], h1s[H_];
  __shared__ float g0s[G4_], g1s[G4_];
  __shared__ float sc[2][S_];
  __shared__ float smax[2], sinv[2];
  __shared__ float lg[2][3];
  int tid = threadIdx.x;
  int b0 = blockIdx.x*2, b1 = b0+1;
  int o2 = tid*2;                 // this thread's 2 gate outputs
  int bsel = tid >> 8;            // 0/1: which batch for the update phase
  int j = tid & 255;              // hidden index for the update phase
  float c_reg = 0.f;              // cell state owned by (bsel, j)
  if (tid < H_) { h0s[tid] = 0.f; h1s[tid] = 0.f; }
  __syncthreads();

  const float* xg0 = g_xg + (size_t)b0*S_*G4_;
  const float* xg1 = g_xg + (size_t)b1*S_*G4_;
  float* ho0 = g_hout + (size_t)b0*S_*H_;
  float* ho1 = g_hout + (size_t)b1*S_*H_;

  for (int s = 0; s < S_; s++) {
    float2 xa = *(const float2*)&xg0[(size_t)s*G4_ + o2];
    float2 xb = *(const float2*)&xg1[(size_t)s*G4_ + o2];
    float a00=xa.x, a01=xa.y, a10=xb.x, a11=xb.y;
    const float* wp = g_WhhT + o2;
    #pragma unroll 2
    for (int k = 0; k < H_; k += 4) {
      float4 ha = *(const float4*)&h0s[k];
      float4 hb = *(const float4*)&h1s[k];
      float2 w;
      w = *(const float2*)&wp[(size_t)(k+0)*G4_];
      a00+=w.x*ha.x; a01+=w.y*ha.x; a10+=w.x*hb.x; a11+=w.y*hb.x;
      w = *(const float2*)&wp[(size_t)(k+1)*G4_];
      a00+=w.x*ha.y; a01+=w.y*ha.y; a10+=w.x*hb.y; a11+=w.y*hb.y;
      w = *(const float2*)&wp[(size_t)(k+2)*G4_];
      a00+=w.x*ha.z; a01+=w.y*ha.z; a10+=w.x*hb.z; a11+=w.y*hb.z;
      w = *(const float2*)&wp[(size_t)(k+3)*G4_];
      a00+=w.x*ha.w; a01+=w.y*ha.w; a10+=w.x*hb.w; a11+=w.y*hb.w;
    }
    g0s[o2]=a00; g0s[o2+1]=a01; g1s[o2]=a10; g1s[o2+1]=a11;
    __syncthreads();
    {
      const float* gs = bsel ? g1s : g0s;
      float gi = gs[j], gf = gs[H_+j], gg = gs[2*H_+j], go = gs[3*H_+j];
      c_reg = sigmf(gf)*c_reg + sigmf(gi)*tanhf(gg);
      float h = sigmf(go)*tanhf(c_reg);
      if (bsel) h1s[j] = h; else h0s[j] = h;
      (bsel ? ho1 : ho0)[(size_t)s*H_ + j] = h;
    }
    __syncthreads();
  }

  // --- attention pooling ---
  int lane = tid & 31, wid = tid >> 5;  // 16 warps
  float ab = attn_b[0];
  for (int s = wid; s < S_; s += 16) {
    float p0 = 0.f, p1 = 0.f;
    for (int r = lane; r < H_; r += 32) {
      float w = attn_w[r];
      p0 += ho0[(size_t)s*H_+r]*w;
      p1 += ho1[(size_t)s*H_+r]*w;
    }
    #pragma unroll
    for (int off = 16; off; off >>= 1) {
      p0 += __shfl_down_sync(0xffffffffu, p0, off);
      p1 += __shfl_down_sync(0xffffffffu, p1, off);
    }
    if (lane == 0) { sc[0][s] = p0+ab; sc[1][s] = p1+ab; }
  }
  if (tid < 6) lg[tid/3][tid%3] = 0.f;
  __syncthreads();

  int len0 = lengths[b0], len1 = lengths[b1];
  if (tid < 2) {
    int len = tid ? len1 : len0;
    float m = -1e30f;
    for (int s = 0; s < len; s++) m = fmaxf(m, sc[tid][s]);
    smax[tid] = m;
  }
  __syncthreads();
  if (tid < 256) {
    int bb = tid >> 7, s = tid & 127;
    int len = bb ? len1 : len0;
    sc[bb][s] = (s < len) ? expf(sc[bb][s]-smax[bb]) : 0.f;
  }
  __syncthreads();
  if (tid < 2) {
    float sum = 0.f;
    for (int s = 0; s < S_; s++) sum += sc[tid][s];
    sinv[tid] = 1.f/sum;
  }
  __syncthreads();
  {
    const float* ho = bsel ? ho1 : ho0;
    float att = 0.f;
    for (int s = 0; s < S_; s++) att += sc[bsel][s]*ho[(size_t)s*H_+j];
    att *= sinv[bsel];
    #pragma unroll
    for (int c = 0; c < 3; c++) atomicAdd(&lg[bsel][c], att*out_w[c*H_+j]);
  }
  __syncthreads();
  if (tid < 6) {
    int bb = tid/3, c = tid%3;
    out[(b0+bb)*3 + c] = lg[bb][c] + out_b[c];
  }
}

// ---------------- launcher ---------------------------------------------------
extern "C" void kernel_launch(void* const* d_in, const int* in_sizes, int n_in,
                              void* d_out, int out_size) {
  const int*   inputs  = (const int*)  d_in[0];
  // d_in[1] = context (unused by the reference)
  const int*   triples = (const int*)  d_in[2];
  const int*   lengths = (const int*)  d_in[3];
  const int*   id2     = (const int*)  d_in[4];
  const float* emb     = (const float*)d_in[5];
  const float* ent     = (const float*)d_in[6];
  const float* rel     = (const float*)d_in[7];
  const float* W_ent   = (const float*)d_in[8];
  const float* W_ih    = (const float*)d_in[9];
  const float* W_hh    = (const float*)d_in[10];
  const float* b_lstm  = (const float*)d_in[11];
  const float* attn_w  = (const float*)d_in[12];
  const float* attn_b  = (const float*)d_in[13];
  const float* out_w   = (const float*)d_in[14];
  const float* out_b   = (const float*)d_in[15];
  float* out = (float*)d_out;

  prep_kernel<<<(KP_*G4_+255)/256, 256>>>(W_ih, W_hh);

  size_t sm1 = (size_t)(200*WTS + T_*200 + T_*D_) * sizeof(float);  // ~92.8 KB
  cudaFuncSetAttribute(graph_tin_kernel,
                       cudaFuncAttributeMaxDynamicSharedMemorySize, (int)sm1);
  graph_tin_kernel<<<NTOK/TOKB, 256, sm1>>>(inputs, triples, id2,
                                            emb, ent, rel, W_ent);

  dim3 g2(G4_/BN, NTOK/BM);
  gemm_xg_kernel<<<g2, 256>>>(b_lstm);

  lstm_attend_kernel<<<B_/2, 512>>>(lengths, attn_w, attn_b, out_w, out_b, out);
}

// round 4
// speedup vs baseline: 1.0566x; 1.0566x over previous
#include <cuda_runtime.h>
#include <math.h>

// Problem constants
#define B_   64
#define S_   128
#define T_   10
#define E_   300
#define D_   100
#define H_   256
#define IN_  500
#define KP_  512          // padded K for the big GEMM
#define G4_  1024         // 4*H
#define NTOK (B_*S_)      // 8192

// ---------------- scratch (static device globals; no runtime alloc) ----------
__device__ float g_WihT[KP_*G4_];          // [512][1024]  (zero-padded rows >= 500)
__device__ float g_WhhT[H_*G4_];           // [256][1024]
__device__ float g_tin[(size_t)NTOK*KP_];  // [8192][512]  (cols 500..511 zero)
__device__ float g_xg[(size_t)NTOK*G4_];   // [8192][1024]
__device__ float g_hout[(size_t)NTOK*H_];  // [64][128][256]

__device__ __forceinline__ float sigmf(float x) { return 1.f/(1.f+expf(-x)); }

// ---------------- prep: transpose W_ih (pad K to 512) and W_hh ---------------
__global__ void prep_kernel(const float* __restrict__ W_ih,
                            const float* __restrict__ W_hh) {
  int idx = blockIdx.x*256 + threadIdx.x;
  if (idx < KP_*G4_) {
    int k = idx >> 10, o = idx & 1023;
    g_WihT[idx] = (k < IN_) ? W_ih[o*IN_ + k] : 0.f;
  }
  if (idx < H_*G4_) {
    int k = idx >> 10, o = idx & 1023;
    g_WhhT[idx] = W_hh[o*H_ + k];
  }
}

// ---------------- K1: graph attention + t_in assembly ------------------------
#define TOKB 8
#define WTS  101   // padded stride for W_ent^T in smem (conflict-free)

__global__ void graph_tin_kernel(const int* __restrict__ inputs,
                                 const int* __restrict__ triples,
                                 const int* __restrict__ id2,
                                 const float* __restrict__ emb,
                                 const float* __restrict__ ent,
                                 const float* __restrict__ rel,
                                 const float* __restrict__ W_ent) {
  extern __shared__ float sm[];
  float* Wt = sm;                   // [200][101]  Wt[k*101+d] = W_ent[d][k]
  float* ht = Wt + 200*WTS;         // [10][200]
  float* er = ht + T_*200;          // [10][100]
  __shared__ float ev[T_];
  __shared__ float alpha[T_];
  __shared__ int   s_valid;
  int tid = threadIdx.x;            // 256 threads

  // load transposed W_ent into smem (stride 101 -> conflict-free stores/loads)
  for (int idx = tid; idx < D_*2*D_; idx += 256) {
    int d = idx / 200, k = idx % 200;
    Wt[k*WTS + d] = W_ent[idx];
  }
  __syncthreads();

  for (int tt = 0; tt < TOKB; tt++) {
    int tok = blockIdx.x*TOKB + tt;
    const int* tri = triples + tok*T_*3;

    // gather ht = [eh || et], er
    for (int idx = tid; idx < T_*200; idx += 256) {
      int t = idx / 200, j = idx % 200;
      int r  = (j < D_) ? tri[t*3] : tri[t*3+1];
      int jj = (j < D_) ? j : j - D_;
      ht[idx] = ent[(size_t)r*D_ + jj];
    }
    for (int idx = tid; idx < T_*D_; idx += 256) {
      int t = idx / D_, j = idx % D_;
      er[idx] = rel[(size_t)tri[t*3+2]*D_ + j];
    }
    if (tid < T_) ev[tid] = 0.f;
    if (tid == 0) {
      int v = 0;
      for (int t = 0; t < T_; t++) v |= (id2[tok*T_+t] != -1);
      s_valid = v;
    }
    __syncthreads();

    // e[t] = sum_d tanh(Wt[:,d] . ht[t]) * er[t][d]
    // thread = (tg, d); tg in {0,1} -> 5 triples each (weight reuse x5)
    if (tid < 200) {
      int d  = tid % D_;
      int tg = tid / D_;
      const float* h0 = ht + (tg*5+0)*200;
      const float* h1 = ht + (tg*5+1)*200;
      const float* h2 = ht + (tg*5+2)*200;
      const float* h3 = ht + (tg*5+3)*200;
      const float* h4 = ht + (tg*5+4)*200;
      float a0=0.f,a1=0.f,a2=0.f,a3=0.f,a4=0.f;
      for (int k = 0; k < 200; k += 4) {
        float4 v0 = *(const float4*)(h0+k);
        float4 v1 = *(const float4*)(h1+k);
        float4 v2 = *(const float4*)(h2+k);
        float4 v3 = *(const float4*)(h3+k);
        float4 v4 = *(const float4*)(h4+k);
        float w0 = Wt[(k+0)*WTS+d];
        float w1 = Wt[(k+1)*WTS+d];
        float w2 = Wt[(k+2)*WTS+d];
        float w3 = Wt[(k+3)*WTS+d];
        a0 += w0*v0.x + w1*v0.y + w2*v0.z + w3*v0.w;
        a1 += w0*v1.x + w1*v1.y + w2*v1.z + w3*v1.w;
        a2 += w0*v2.x + w1*v2.y + w2*v2.z + w3*v2.w;
        a3 += w0*v3.x + w1*v3.y + w2*v3.z + w3*v3.w;
        a4 += w0*v4.x + w1*v4.y + w2*v4.z + w3*v4.w;
      }
      atomicAdd(&ev[tg*5+0], tanhf(a0)*er[(tg*5+0)*D_+d]);
      atomicAdd(&ev[tg*5+1], tanhf(a1)*er[(tg*5+1)*D_+d]);
      atomicAdd(&ev[tg*5+2], tanhf(a2)*er[(tg*5+2)*D_+d]);
      atomicAdd(&ev[tg*5+3], tanhf(a3)*er[(tg*5+3)*D_+d]);
      atomicAdd(&ev[tg*5+4], tanhf(a4)*er[(tg*5+4)*D_+d]);
    }
    __syncthreads();

    if (tid == 0) {  // softmax over 10 triples
      float mx = ev[0];
      for (int t = 1; t < T_; t++) mx = fmaxf(mx, ev[t]);
      float sum = 0.f;
      for (int t = 0; t < T_; t++) { float e = expf(ev[t]-mx); alpha[t]=e; sum+=e; }
      float inv = 1.f/sum;
      for (int t = 0; t < T_; t++) alpha[t] *= inv;
    }
    __syncthreads();

    // write t_in row: [x(300) | graph(200) | pad(12)=0]
    float* row = g_tin + (size_t)tok*KP_;
    const float* xr = emb + (size_t)inputs[tok]*E_;
    for (int j = tid; j < E_; j += 256) row[j] = xr[j];
    float vm = s_valid ? 1.f : 0.f;
    for (int j = tid; j < 200; j += 256) {
      float g = 0.f;
      #pragma unroll
      for (int t = 0; t < T_; t++) g += alpha[t]*ht[t*200+j];
      row[E_+j] = g*vm;
    }
    if (tid < KP_-IN_) row[IN_+tid] = 0.f;
    __syncthreads();  // protect ht before next token overwrites it
  }
}

// ---------------- K2: xg = t_in @ W_ih^T + b  (SGEMM 8192x1024x512) ----------
#define BM 64
#define BN 64
#define BK 16

__global__ __launch_bounds__(256) void gemm_xg_kernel(const float* __restrict__ bias) {
  __shared__ float As[BK][BM+4];
  __shared__ float Bs[BK][BN];
  int tid = threadIdx.x;
  int tx = tid & 15, ty = tid >> 4;
  int bm = blockIdx.y * BM, bn = blockIdx.x * BN;
  int arow = tid >> 2, acol = (tid & 3) << 2;
  int brow = tid >> 4, bcol = (tid & 15) << 2;
  const float* Ab = g_tin + (size_t)bm*KP_;
  float acc[4][4] = {};
  for (int k0 = 0; k0 < KP_; k0 += BK) {
    float4 av = *(const float4*)&Ab[(size_t)arow*KP_ + k0 + acol];
    As[acol+0][arow]=av.x; As[acol+1][arow]=av.y;
    As[acol+2][arow]=av.z; As[acol+3][arow]=av.w;
    *(float4*)&Bs[brow][bcol] = *(const float4*)&g_WihT[(size_t)(k0+brow)*G4_ + bn + bcol];
    __syncthreads();
    #pragma unroll
    for (int k = 0; k < BK; k++) {
      float a0 = As[k][ty*4+0], a1 = As[k][ty*4+1];
      float a2 = As[k][ty*4+2], a3 = As[k][ty*4+3];
      float b0 = Bs[k][tx*4+0], b1 = Bs[k][tx*4+1];
      float b2 = Bs[k][tx*4+2], b3 = Bs[k][tx*4+3];
      acc[0][0]+=a0*b0; acc[0][1]+=a0*b1; acc[0][2]+=a0*b2; acc[0][3]+=a0*b3;
      acc[1][0]+=a1*b0; acc[1][1]+=a1*b1; acc[1][2]+=a1*b2; acc[1][3]+=a1*b3;
      acc[2][0]+=a2*b0; acc[2][1]+=a2*b1; acc[2][2]+=a2*b2; acc[2][3]+=a2*b3;
      acc[3][0]+=a3*b0; acc[3][1]+=a3*b1; acc[3][2]+=a3*b2; acc[3][3]+=a3*b3;
    }
    __syncthreads();
  }
  #pragma unroll
  for (int i = 0; i < 4; i++) {
    int r = bm + ty*4 + i;
    int cc = bn + tx*4;
    float4 o;
    o.x = acc[i][0] + bias[cc+0];
    o.y = acc[i][1] + bias[cc+1];
    o.z = acc[i][2] + bias[cc+2];
    o.w = acc[i][3] + bias[cc+3];
    *(float4*)&g_xg[(size_t)r*G4_ + cc] = o;
  }
}

// ---------------- K3: LSTM scan + masked attention pooling + logits ----------
// 32 blocks x 512 threads; each block owns 2 batches (W_hh load reused x2).
__global__ __launch_bounds__(512) void lstm_attend_kernel(
    const int*   __restrict__ lengths,
    const float* __restrict__ attn_w,
    const float* __restrict__ attn_b,
    const float* __restrict__ out_w,
    const float* __restrict__ out_b,
    float*       __restrict__ out) {
  __shared__ float h0s[H_], h1s[H_];
  __shared__ float g0s[G4_], g1s[G4_];
  __shared__ float sc[2][S_];
  __shared__ float smax[2], sinv[2];
  __shared__ float lg[2][3];
  int tid = threadIdx.x;
  int b0 = blockIdx.x*2, b1 = b0+1;
  int o2 = tid*2;                 // this thread's 2 gate outputs
  int bsel = tid >> 8;            // 0/1: which batch for the update phase
  int j = tid & 255;              // hidden index for the update phase
  float c_reg = 0.f;              // cell state owned by (bsel, j)
  if (tid < H_) { h0s[tid] = 0.f; h1s[tid] = 0.f; }
  __syncthreads();

  const float* xg0 = g_xg + (size_t)b0*S_*G4_;
  const float* xg1 = g_xg + (size_t)b1*S_*G4_;
  float* ho0 = g_hout + (size_t)b0*S_*H_;
  float* ho1 = g_hout + (size_t)b1*S_*H_;

  for (int s = 0; s < S_; s++) {
    float2 xa = *(const float2*)&xg0[(size_t)s*G4_ + o2];
    float2 xb = *(const float2*)&xg1[(size_t)s*G4_ + o2];
    float a00=xa.x, a01=xa.y, a10=xb.x, a11=xb.y;
    const float* wp = g_WhhT + o2;
    #pragma unroll 2
    for (int k = 0; k < H_; k += 4) {
      float4 ha = *(const float4*)&h0s[k];
      float4 hb = *(const float4*)&h1s[k];
      float2 w;
      w = *(const float2*)&wp[(size_t)(k+0)*G4_];
      a00+=w.x*ha.x; a01+=w.y*ha.x; a10+=w.x*hb.x; a11+=w.y*hb.x;
      w = *(const float2*)&wp[(size_t)(k+1)*G4_];
      a00+=w.x*ha.y; a01+=w.y*ha.y; a10+=w.x*hb.y; a11+=w.y*hb.y;
      w = *(const float2*)&wp[(size_t)(k+2)*G4_];
      a00+=w.x*ha.z; a01+=w.y*ha.z; a10+=w.x*hb.z; a11+=w.y*hb.z;
      w = *(const float2*)&wp[(size_t)(k+3)*G4_];
      a00+=w.x*ha.w; a01+=w.y*ha.w; a10+=w.x*hb.w; a11+=w.y*hb.w;
    }
    g0s[o2]=a00; g0s[o2+1]=a01; g1s[o2]=a10; g1s[o2+1]=a11;
    __syncthreads();
    {
      const float* gs = bsel ? g1s : g0s;
      float gi = gs[j], gf = gs[H_+j], gg = gs[2*H_+j], go = gs[3*H_+j];
      c_reg = sigmf(gf)*c_reg + sigmf(gi)*tanhf(gg);
      float h = sigmf(go)*tanhf(c_reg);
      if (bsel) h1s[j] = h; else h0s[j] = h;
      (bsel ? ho1 : ho0)[(size_t)s*H_ + j] = h;
    }
    __syncthreads();
  }

  // --- attention pooling ---
  int lane = tid & 31, wid = tid >> 5;  // 16 warps
  float ab = attn_b[0];
  for (int s = wid; s < S_; s += 16) {
    float p0 = 0.f, p1 = 0.f;
    for (int r = lane; r < H_; r += 32) {
      float w = attn_w[r];
      p0 += ho0[(size_t)s*H_+r]*w;
      p1 += ho1[(size_t)s*H_+r]*w;
    }
    #pragma unroll
    for (int off = 16; off; off >>= 1) {
      p0 += __shfl_down_sync(0xffffffffu, p0, off);
      p1 += __shfl_down_sync(0xffffffffu, p1, off);
    }
    if (lane == 0) { sc[0][s] = p0+ab; sc[1][s] = p1+ab; }
  }
  if (tid < 6) lg[tid/3][tid%3] = 0.f;
  __syncthreads();

  int len0 = lengths[b0], len1 = lengths[b1];
  if (tid < 2) {
    int len = tid ? len1 : len0;
    float m = -1e30f;
    for (int s = 0; s < len; s++) m = fmaxf(m, sc[tid][s]);
    smax[tid] = m;
  }
  __syncthreads();
  if (tid < 256) {
    int bb = tid >> 7, s = tid & 127;
    int len = bb ? len1 : len0;
    sc[bb][s] = (s < len) ? expf(sc[bb][s]-smax[bb]) : 0.f;
  }
  __syncthreads();
  if (tid < 2) {
    float sum = 0.f;
    for (int s = 0; s < S_; s++) sum += sc[tid][s];
    sinv[tid] = 1.f/sum;
  }
  __syncthreads();
  {
    const float* ho = bsel ? ho1 : ho0;
    float att = 0.f;
    for (int s = 0; s < S_; s++) att += sc[bsel][s]*ho[(size_t)s*H_+j];
    att *= sinv[bsel];
    #pragma unroll
    for (int c = 0; c < 3; c++) atomicAdd(&lg[bsel][c], att*out_w[c*H_+j]);
  }
  __syncthreads();
  if (tid < 6) {
    int bb = tid/3, c = tid%3;
    out[(b0+bb)*3 + c] = lg[bb][c] + out_b[c];
  }
}

// ---------------- launcher ---------------------------------------------------
extern "C" void kernel_launch(void* const* d_in, const int* in_sizes, int n_in,
                              void* d_out, int out_size) {
  const int*   inputs  = (const int*)  d_in[0];
  // d_in[1] = context (unused by the reference)
  const int*   triples = (const int*)  d_in[2];
  const int*   lengths = (const int*)  d_in[3];
  const int*   id2     = (const int*)  d_in[4];
  const float* emb     = (const float*)d_in[5];
  const float* ent     = (const float*)d_in[6];
  const float* rel     = (const float*)d_in[7];
  const float* W_ent   = (const float*)d_in[8];
  const float* W_ih    = (const float*)d_in[9];
  const float* W_hh    = (const float*)d_in[10];
  const float* b_lstm  = (const float*)d_in[11];
  const float* attn_w  = (const float*)d_in[12];
  const float* attn_b  = (const float*)d_in[13];
  const float* out_w   = (const float*)d_in[14];
  const float* out_b   = (const float*)d_in[15];
  float* out = (float*)d_out;

  prep_kernel<<<(KP_*G4_+255)/256, 256>>>(W_ih, W_hh);

  size_t sm1 = (size_t)(200*WTS + T_*200 + T_*D_) * sizeof(float);  // ~92.8 KB
  cudaFuncSetAttribute(graph_tin_kernel,
                       cudaFuncAttributeMaxDynamicSharedMemorySize, (int)sm1);
  graph_tin_kernel<<<NTOK/TOKB, 256, sm1>>>(inputs, triples, id2,
                                            emb, ent, rel, W_ent);

  dim3 g2(G4_/BN, NTOK/BM);
  gemm_xg_kernel<<<g2, 256>>>(b_lstm);

  lstm_attend_kernel<<<B_/2, 512>>>(lengths, attn_w, attn_b, out_w, out_b, out);
}

// round 12
// speedup vs baseline: 1.3109x; 1.2407x over previous
#include <cuda_runtime.h>
#include <math.h>
#include <stdint.h>

// Problem constants
#define B_   64
#define S_   128
#define T_   10
#define E_   300
#define D_   100
#define H_   256
#define IN_  500
#define KP_  512          // padded K for the big GEMM
#define G4_  1024         // 4*H
#define NTOK (B_*S_)      // 8192

// ---------------- scratch (static device globals; no runtime alloc) ----------
__device__ float g_WihT[KP_*G4_];          // [512][1024]  (zero-padded rows >= 500)
__device__ float g_WhhP[H_*G4_];           // [128][1024][2] pair-interleaved W_hh
__device__ float g_tin[(size_t)NTOK*KP_];  // [8192][512]  (cols 500..511 zero)
__device__ float g_xg[(size_t)NTOK*G4_];   // [8192][1024]
__device__ float g_hout[(size_t)NTOK*H_];  // [64][128][256]

__device__ __forceinline__ float sigmf(float x) { return 1.f/(1.f+expf(-x)); }

// packed fp32x2 FMA: acc += a*b elementwise on two packed fp32 lanes
__device__ __forceinline__ void fma2(unsigned long long& acc,
                                     unsigned long long a,
                                     unsigned long long b) {
  asm("fma.rn.f32x2 %0, %1, %2, %0;" : "+l"(acc) : "l"(a), "l"(b));
}
__device__ __forceinline__ float2 unpack2(unsigned long long v) {
  float2 f;
  asm("mov.b64 {%0, %1}, %2;" : "=f"(f.x), "=f"(f.y) : "l"(v));
  return f;
}

// ---------------- prep: transpose W_ih (pad K to 512); pair-pack W_hh --------
__global__ void prep_kernel(const float* __restrict__ W_ih,
                            const float* __restrict__ W_hh) {
  int idx = blockIdx.x*256 + threadIdx.x;
  if (idx < KP_*G4_) {
    int k = idx >> 10, o = idx & 1023;
    g_WihT[idx] = (k < IN_) ? W_ih[o*IN_ + k] : 0.f;
  }
  if (idx < H_*G4_) {
    // layout [k2][o][p]: idx = (k2*1024 + o)*2 + p
    int k2 = idx >> 11;
    int r  = idx & 2047;
    int o  = r >> 1;
    int p  = r & 1;
    g_WhhP[idx] = W_hh[o*H_ + (k2*2 + p)];
  }
}

// ---------------- K1: graph attention + t_in assembly ------------------------
#define TOKB 8
#define WTS  101   // padded stride for W_ent^T in smem (conflict-free)

__global__ void graph_tin_kernel(const int* __restrict__ inputs,
                                 const int* __restrict__ triples,
                                 const int* __restrict__ id2,
                                 const float* __restrict__ emb,
                                 const float* __restrict__ ent,
                                 const float* __restrict__ rel,
                                 const float* __restrict__ W_ent) {
  extern __shared__ float sm[];
  float* Wt = sm;                   // [200][101]  Wt[k*101+d] = W_ent[d][k]
  float* ht = Wt + 200*WTS;         // [10][200]
  float* er = ht + T_*200;          // [10][100]
  __shared__ float ev[T_];
  __shared__ float alpha[T_];
  __shared__ int   s_valid;
  int tid = threadIdx.x;            // 256 threads

  for (int idx = tid; idx < D_*2*D_; idx += 256) {
    int d = idx / 200, k = idx % 200;
    Wt[k*WTS + d] = W_ent[idx];
  }
  __syncthreads();

  for (int tt = 0; tt < TOKB; tt++) {
    int tok = blockIdx.x*TOKB + tt;
    const int* tri = triples + tok*T_*3;

    for (int idx = tid; idx < T_*200; idx += 256) {
      int t = idx / 200, j = idx % 200;
      int r  = (j < D_) ? tri[t*3] : tri[t*3+1];
      int jj = (j < D_) ? j : j - D_;
      ht[idx] = ent[(size_t)r*D_ + jj];
    }
    for (int idx = tid; idx < T_*D_; idx += 256) {
      int t = idx / D_, j = idx % D_;
      er[idx] = rel[(size_t)tri[t*3+2]*D_ + j];
    }
    if (tid < T_) ev[tid] = 0.f;
    if (tid == 0) {
      int v = 0;
      for (int t = 0; t < T_; t++) v |= (id2[tok*T_+t] != -1);
      s_valid = v;
    }
    __syncthreads();

    if (tid < 200) {
      int d  = tid % D_;
      int tg = tid / D_;
      const float* h0 = ht + (tg*5+0)*200;
      const float* h1 = ht + (tg*5+1)*200;
      const float* h2 = ht + (tg*5+2)*200;
      const float* h3 = ht + (tg*5+3)*200;
      const float* h4 = ht + (tg*5+4)*200;
      float a0=0.f,a1=0.f,a2=0.f,a3=0.f,a4=0.f;
      for (int k = 0; k < 200; k += 4) {
        float4 v0 = *(const float4*)(h0+k);
        float4 v1 = *(const float4*)(h1+k);
        float4 v2 = *(const float4*)(h2+k);
        float4 v3 = *(const float4*)(h3+k);
        float4 v4 = *(const float4*)(h4+k);
        float w0 = Wt[(k+0)*WTS+d];
        float w1 = Wt[(k+1)*WTS+d];
        float w2 = Wt[(k+2)*WTS+d];
        float w3 = Wt[(k+3)*WTS+d];
        a0 += w0*v0.x + w1*v0.y + w2*v0.z + w3*v0.w;
        a1 += w0*v1.x + w1*v1.y + w2*v1.z + w3*v1.w;
        a2 += w0*v2.x + w1*v2.y + w2*v2.z + w3*v2.w;
        a3 += w0*v3.x + w1*v3.y + w2*v3.z + w3*v3.w;
        a4 += w0*v4.x + w1*v4.y + w2*v4.z + w3*v4.w;
      }
      atomicAdd(&ev[tg*5+0], tanhf(a0)*er[(tg*5+0)*D_+d]);
      atomicAdd(&ev[tg*5+1], tanhf(a1)*er[(tg*5+1)*D_+d]);
      atomicAdd(&ev[tg*5+2], tanhf(a2)*er[(tg*5+2)*D_+d]);
      atomicAdd(&ev[tg*5+3], tanhf(a3)*er[(tg*5+3)*D_+d]);
      atomicAdd(&ev[tg*5+4], tanhf(a4)*er[(tg*5+4)*D_+d]);
    }
    __syncthreads();

    if (tid == 0) {
      float mx = ev[0];
      for (int t = 1; t < T_; t++) mx = fmaxf(mx, ev[t]);
      float sum = 0.f;
      for (int t = 0; t < T_; t++) { float e = expf(ev[t]-mx); alpha[t]=e; sum+=e; }
      float inv = 1.f/sum;
      for (int t = 0; t < T_; t++) alpha[t] *= inv;
    }
    __syncthreads();

    float* row = g_tin + (size_t)tok*KP_;
    const float* xr = emb + (size_t)inputs[tok]*E_;
    for (int j = tid; j < E_; j += 256) row[j] = xr[j];
    float vm = s_valid ? 1.f : 0.f;
    for (int j = tid; j < 200; j += 256) {
      float g = 0.f;
      #pragma unroll
      for (int t = 0; t < T_; t++) g += alpha[t]*ht[t*200+j];
      row[E_+j] = g*vm;
    }
    if (tid < KP_-IN_) row[IN_+tid] = 0.f;
    __syncthreads();
  }
}

// ---------------- K2: xg = t_in @ W_ih^T + b  (SGEMM 8192x1024x512) ----------
#define BM 64
#define BN 64
#define BK 16

__global__ __launch_bounds__(256) void gemm_xg_kernel(const float* __restrict__ bias) {
  __shared__ float As[BK][BM+4];
  __shared__ float Bs[BK][BN];
  int tid = threadIdx.x;
  int tx = tid & 15, ty = tid >> 4;
  int bm = blockIdx.y * BM, bn = blockIdx.x * BN;
  int arow = tid >> 2, acol = (tid & 3) << 2;
  int brow = tid >> 4, bcol = (tid & 15) << 2;
  const float* Ab = g_tin + (size_t)bm*KP_;
  float acc[4][4] = {};
  for (int k0 = 0; k0 < KP_; k0 += BK) {
    float4 av = *(const float4*)&Ab[(size_t)arow*KP_ + k0 + acol];
    As[acol+0][arow]=av.x; As[acol+1][arow]=av.y;
    As[acol+2][arow]=av.z; As[acol+3][arow]=av.w;
    *(float4*)&Bs[brow][bcol] = *(const float4*)&g_WihT[(size_t)(k0+brow)*G4_ + bn + bcol];
    __syncthreads();
    #pragma unroll
    for (int k = 0; k < BK; k++) {
      float a0 = As[k][ty*4+0], a1 = As[k][ty*4+1];
      float a2 = As[k][ty*4+2], a3 = As[k][ty*4+3];
      float b0 = Bs[k][tx*4+0], b1 = Bs[k][tx*4+1];
      float b2 = Bs[k][tx*4+2], b3 = Bs[k][tx*4+3];
      acc[0][0]+=a0*b0; acc[0][1]+=a0*b1; acc[0][2]+=a0*b2; acc[0][3]+=a0*b3;
      acc[1][0]+=a1*b0; acc[1][1]+=a1*b1; acc[1][2]+=a1*b2; acc[1][3]+=a1*b3;
      acc[2][0]+=a2*b0; acc[2][1]+=a2*b1; acc[2][2]+=a2*b2; acc[2][3]+=a2*b3;
      acc[3][0]+=a3*b0; acc[3][1]+=a3*b1; acc[3][2]+=a3*b2; acc[3][3]+=a3*b3;
    }
    __syncthreads();
  }
  #pragma unroll
  for (int i = 0; i < 4; i++) {
    int r = bm + ty*4 + i;
    int cc = bn + tx*4;
    float4 o;
    o.x = acc[i][0] + bias[cc+0];
    o.y = acc[i][1] + bias[cc+1];
    o.z = acc[i][2] + bias[cc+2];
    o.w = acc[i][3] + bias[cc+3];
    *(float4*)&g_xg[(size_t)r*G4_ + cc] = o;
  }
}

// ---------------- K3: LSTM scan v2 (no clusters) ------------------------------
// 32 CTAs x 512 threads, 2 batches/CTA. Weights streamed from L2 via coalesced
// LDG.128 on a pair-interleaved layout; gate math in packed fp32x2.
// Per step per SM: 1MB weight stream (~8192 cyc @128B/cyc) fully overlapping
// 4096 cyc of FFMA2 — L1-return-bandwidth bound.
__global__ __launch_bounds__(512) void lstm2_kernel(float*) {
  __shared__ float hbuf[2][H_];     // current h per batch
  __shared__ float pre[2][G4_];     // gate pre-activations per batch

  int tid = threadIdx.x;            // 512
  int b0  = blockIdx.x*2;
  int o2  = tid*2;                  // this thread's 2 gate outputs
  int ub  = tid >> 8;               // update phase: batch
  int uj  = tid & 255;              // update phase: hidden index
  float c = 0.f;

  if (tid < H_) { hbuf[0][tid] = 0.f; hbuf[1][tid] = 0.f; }
  __syncthreads();

  // Wp element t at k2 = pair (w[o2][2k2], w[o2][2k2+1]) , (w[o2+1][2k2], w[o2+1][2k2+1])
  const ulonglong2* Wp = ((const ulonglong2*)g_WhhP) + tid;
  const float* xg0 = g_xg + (size_t)b0*S_*G4_ + o2;
  const float* xg1 = g_xg + (size_t)(b0+1)*S_*G4_ + o2;
  float* ho = g_hout + (size_t)b0*S_*H_;

  for (int s = 0; s < S_; s++) {
    float2 x0 = *(const float2*)&xg0[(size_t)s*G4_];
    float2 x1 = *(const float2*)&xg1[(size_t)s*G4_];

    unsigned long long a00=0ULL, a01=0ULL, a10=0ULL, a11=0ULL;
    #pragma unroll 4
    for (int k2 = 0; k2 < H_/2; k2++) {
      ulonglong2 w = Wp[(size_t)k2*(G4_/2)];
      unsigned long long h0 = *(const unsigned long long*)&hbuf[0][k2*2];
      unsigned long long h1 = *(const unsigned long long*)&hbuf[1][k2*2];
      fma2(a00, w.x, h0);
      fma2(a01, w.y, h0);
      fma2(a10, w.x, h1);
      fma2(a11, w.y, h1);
    }
    float2 f00 = unpack2(a00), f01 = unpack2(a01);
    float2 f10 = unpack2(a10), f11 = unpack2(a11);
    *(float2*)&pre[0][o2] = make_float2(f00.x + f00.y + x0.x, f01.x + f01.y + x0.y);
    *(float2*)&pre[1][o2] = make_float2(f10.x + f10.y + x1.x, f11.x + f11.y + x1.y);
    __syncthreads();

    {
      float gi = pre[ub][uj],       gf = pre[ub][H_+uj];
      float gg = pre[ub][2*H_+uj],  go = pre[ub][3*H_+uj];
      c = sigmf(gf)*c + sigmf(gi)*tanhf(gg);
      float h = sigmf(go)*tanhf(c);
      hbuf[ub][uj] = h;
      ho[((size_t)ub*S_ + s)*H_ + uj] = h;
    }
    __syncthreads();
  }
}

// ---------------- K4: masked attention pooling + logits ----------------------
__global__ __launch_bounds__(256) void attend_kernel(
    const int*   __restrict__ lengths,
    const float* __restrict__ attn_w,
    const float* __restrict__ attn_b,
    const float* __restrict__ out_w,
    const float* __restrict__ out_b,
    float*       __restrict__ out) {
  __shared__ float sw[H_];
  __shared__ float sc[S_];
  __shared__ float smax, sinv;
  __shared__ float lg[3];
  int tid = threadIdx.x;
  int b = blockIdx.x;
  const float* ho = g_hout + (size_t)b*S_*H_;

  sw[tid] = attn_w[tid];
  if (tid < 3) lg[tid] = 0.f;
  __syncthreads();

  int lane = tid & 31, wid = tid >> 5;  // 8 warps
  float ab = attn_b[0];
  for (int s = wid; s < S_; s += 8) {
    float p = 0.f;
    for (int k = lane; k < H_; k += 32) p += ho[(size_t)s*H_ + k]*sw[k];
    #pragma unroll
    for (int off = 16; off; off >>= 1) p += __shfl_down_sync(0xffffffffu, p, off);
    if (lane == 0) sc[s] = p + ab;
  }
  __syncthreads();

  int len = lengths[b];
  if (tid == 0) {
    float m = -1e30f;
    for (int s = 0; s < len; s++) m = fmaxf(m, sc[s]);
    smax = m;
  }
  __syncthreads();
  if (tid < S_) sc[tid] = (tid < len) ? expf(sc[tid]-smax) : 0.f;
  __syncthreads();
  if (tid == 0) {
    float sum = 0.f;
    for (int s = 0; s < S_; s++) sum += sc[s];
    sinv = 1.f/sum;
  }
  __syncthreads();

  float att = 0.f;
  for (int s = 0; s < S_; s++) att += sc[s]*ho[(size_t)s*H_ + tid];
  att *= sinv;
  #pragma unroll
  for (int c = 0; c < 3; c++) atomicAdd(&lg[c], att*out_w[c*H_ + tid]);
  __syncthreads();
  if (tid < 3) out[b*3 + tid] = lg[tid] + out_b[tid];
}

// ---------------- launcher ---------------------------------------------------
extern "C" void kernel_launch(void* const* d_in, const int* in_sizes, int n_in,
                              void* d_out, int out_size) {
  const int*   inputs  = (const int*)  d_in[0];
  // d_in[1] = context (unused by the reference)
  const int*   triples = (const int*)  d_in[2];
  const int*   lengths = (const int*)  d_in[3];
  const int*   id2     = (const int*)  d_in[4];
  const float* emb     = (const float*)d_in[5];
  const float* ent     = (const float*)d_in[6];
  const float* rel     = (const float*)d_in[7];
  const float* W_ent   = (const float*)d_in[8];
  const float* W_ih    = (const float*)d_in[9];
  const float* W_hh    = (const float*)d_in[10];
  const float* b_lstm  = (const float*)d_in[11];
  const float* attn_w  = (const float*)d_in[12];
  const float* attn_b  = (const float*)d_in[13];
  const float* out_w   = (const float*)d_in[14];
  const float* out_b   = (const float*)d_in[15];
  float* out = (float*)d_out;

  prep_kernel<<<(KP_*G4_+255)/256, 256>>>(W_ih, W_hh);

  size_t sm1 = (size_t)(200*WTS + T_*200 + T_*D_) * sizeof(float);  // ~92.8 KB
  cudaFuncSetAttribute(graph_tin_kernel,
                       cudaFuncAttributeMaxDynamicSharedMemorySize, (int)sm1);
  graph_tin_kernel<<<NTOK/TOKB, 256, sm1>>>(inputs, triples, id2,
                                            emb, ent, rel, W_ent);

  dim3 g2(G4_/BN, NTOK/BM);
  gemm_xg_kernel<<<g2, 256>>>(b_lstm);

  lstm2_kernel<<<B_/2, 512>>>(out);

  attend_kernel<<<B_, 256>>>(lengths, attn_w, attn_b, out_w, out_b, out);
}

// round 13
// speedup vs baseline: 2.0505x; 1.5642x over previous
#include <cuda_runtime.h>
#include <math.h>
#include <stdint.h>

// Problem constants
#define B_   64
#define S_   128
#define T_   10
#define E_   300
#define D_   100
#define H_   256
#define IN_  500
#define KP_  512          // padded K for the big GEMM
#define G4_  1024         // 4*H
#define NTOK (B_*S_)      // 8192
#define NCTA 128          // persistent LSTM CTAs

// ---------------- scratch (static device globals; no runtime alloc) ----------
__device__ float g_WihT[KP_*G4_];           // [512][1024] (zero-padded rows >= 500)
__device__ float g_tin[(size_t)NTOK*KP_];   // [8192][512]
__device__ float g_xg[(size_t)NTOK*G4_];    // [8192][1024]  (b,s,o)
__device__ float g_xgT[(size_t)S_*G4_*B_];  // [128][1024][64] (s,o,b)
__device__ float g_hout[(size_t)NTOK*H_];   // [64][128][256]
__device__ float g_hT[2][H_][B_];           // double-buffered h, transposed [k][b]
__device__ int   g_cnt[S_];                 // per-step arrival counters

__device__ __forceinline__ float sigmf(float x) { return 1.f/(1.f+expf(-x)); }

// packed fp32x2 FMA: acc += a*b elementwise on two packed fp32 lanes
__device__ __forceinline__ void fma2(unsigned long long& acc,
                                     unsigned long long a,
                                     unsigned long long b) {
  asm("fma.rn.f32x2 %0, %1, %2, %0;" : "+l"(acc) : "l"(a), "l"(b));
}

// ---------------- prep: transpose W_ih; zero hT buf0 + step counters ---------
__global__ void prep_kernel(const float* __restrict__ W_ih) {
  int idx = blockIdx.x*256 + threadIdx.x;
  if (idx < KP_*G4_) {
    int k = idx >> 10, o = idx & 1023;
    g_WihT[idx] = (k < IN_) ? W_ih[o*IN_ + k] : 0.f;
  }
  if (idx < H_*B_) ((float*)g_hT)[idx] = 0.f;   // buffer 0 only
  if (idx < S_)    g_cnt[idx] = 0;
}

// ---------------- K1: graph attention + t_in assembly ------------------------
#define TOKB 8
#define WTS  101   // padded stride for W_ent^T in smem (conflict-free)

__global__ void graph_tin_kernel(const int* __restrict__ inputs,
                                 const int* __restrict__ triples,
                                 const int* __restrict__ id2,
                                 const float* __restrict__ emb,
                                 const float* __restrict__ ent,
                                 const float* __restrict__ rel,
                                 const float* __restrict__ W_ent) {
  extern __shared__ float sm[];
  float* Wt = sm;                   // [200][101]
  float* ht = Wt + 200*WTS;         // [10][200]
  float* er = ht + T_*200;          // [10][100]
  __shared__ float ev[T_];
  __shared__ float alpha[T_];
  __shared__ int   s_valid;
  int tid = threadIdx.x;            // 256 threads

  for (int idx = tid; idx < D_*2*D_; idx += 256) {
    int d = idx / 200, k = idx % 200;
    Wt[k*WTS + d] = W_ent[idx];
  }
  __syncthreads();

  for (int tt = 0; tt < TOKB; tt++) {
    int tok = blockIdx.x*TOKB + tt;
    const int* tri = triples + tok*T_*3;

    for (int idx = tid; idx < T_*200; idx += 256) {
      int t = idx / 200, j = idx % 200;
      int r  = (j < D_) ? tri[t*3] : tri[t*3+1];
      int jj = (j < D_) ? j : j - D_;
      ht[idx] = ent[(size_t)r*D_ + jj];
    }
    for (int idx = tid; idx < T_*D_; idx += 256) {
      int t = idx / D_, j = idx % D_;
      er[idx] = rel[(size_t)tri[t*3+2]*D_ + j];
    }
    if (tid < T_) ev[tid] = 0.f;
    if (tid == 0) {
      int v = 0;
      for (int t = 0; t < T_; t++) v |= (id2[tok*T_+t] != -1);
      s_valid = v;
    }
    __syncthreads();

    if (tid < 200) {
      int d  = tid % D_;
      int tg = tid / D_;
      const float* h0 = ht + (tg*5+0)*200;
      const float* h1 = ht + (tg*5+1)*200;
      const float* h2 = ht + (tg*5+2)*200;
      const float* h3 = ht + (tg*5+3)*200;
      const float* h4 = ht + (tg*5+4)*200;
      float a0=0.f,a1=0.f,a2=0.f,a3=0.f,a4=0.f;
      for (int k = 0; k < 200; k += 4) {
        float4 v0 = *(const float4*)(h0+k);
        float4 v1 = *(const float4*)(h1+k);
        float4 v2 = *(const float4*)(h2+k);
        float4 v3 = *(const float4*)(h3+k);
        float4 v4 = *(const float4*)(h4+k);
        float w0 = Wt[(k+0)*WTS+d];
        float w1 = Wt[(k+1)*WTS+d];
        float w2 = Wt[(k+2)*WTS+d];
        float w3 = Wt[(k+3)*WTS+d];
        a0 += w0*v0.x + w1*v0.y + w2*v0.z + w3*v0.w;
        a1 += w0*v1.x + w1*v1.y + w2*v1.z + w3*v1.w;
        a2 += w0*v2.x + w1*v2.y + w2*v2.z + w3*v2.w;
        a3 += w0*v3.x + w1*v3.y + w2*v3.z + w3*v3.w;
        a4 += w0*v4.x + w1*v4.y + w2*v4.z + w3*v4.w;
      }
      atomicAdd(&ev[tg*5+0], tanhf(a0)*er[(tg*5+0)*D_+d]);
      atomicAdd(&ev[tg*5+1], tanhf(a1)*er[(tg*5+1)*D_+d]);
      atomicAdd(&ev[tg*5+2], tanhf(a2)*er[(tg*5+2)*D_+d]);
      atomicAdd(&ev[tg*5+3], tanhf(a3)*er[(tg*5+3)*D_+d]);
      atomicAdd(&ev[tg*5+4], tanhf(a4)*er[(tg*5+4)*D_+d]);
    }
    __syncthreads();

    if (tid == 0) {
      float mx = ev[0];
      for (int t = 1; t < T_; t++) mx = fmaxf(mx, ev[t]);
      float sum = 0.f;
      for (int t = 0; t < T_; t++) { float e = expf(ev[t]-mx); alpha[t]=e; sum+=e; }
      float inv = 1.f/sum;
      for (int t = 0; t < T_; t++) alpha[t] *= inv;
    }
    __syncthreads();

    float* row = g_tin + (size_t)tok*KP_;
    const float* xr = emb + (size_t)inputs[tok]*E_;
    for (int j = tid; j < E_; j += 256) row[j] = xr[j];
    float vm = s_valid ? 1.f : 0.f;
    for (int j = tid; j < 200; j += 256) {
      float g = 0.f;
      #pragma unroll
      for (int t = 0; t < T_; t++) g += alpha[t]*ht[t*200+j];
      row[E_+j] = g*vm;
    }
    if (tid < KP_-IN_) row[IN_+tid] = 0.f;
    __syncthreads();
  }
}

// ---------------- K2: xg = t_in @ W_ih^T + b  (SGEMM 8192x1024x512) ----------
#define BM 64
#define BN 64
#define BK 16

__global__ __launch_bounds__(256) void gemm_xg_kernel(const float* __restrict__ bias) {
  __shared__ float As[BK][BM+4];
  __shared__ float Bs[BK][BN];
  int tid = threadIdx.x;
  int tx = tid & 15, ty = tid >> 4;
  int bm = blockIdx.y * BM, bn = blockIdx.x * BN;
  int arow = tid >> 2, acol = (tid & 3) << 2;
  int brow = tid >> 4, bcol = (tid & 15) << 2;
  const float* Ab = g_tin + (size_t)bm*KP_;
  float acc[4][4] = {};
  for (int k0 = 0; k0 < KP_; k0 += BK) {
    float4 av = *(const float4*)&Ab[(size_t)arow*KP_ + k0 + acol];
    As[acol+0][arow]=av.x; As[acol+1][arow]=av.y;
    As[acol+2][arow]=av.z; As[acol+3][arow]=av.w;
    *(float4*)&Bs[brow][bcol] = *(const float4*)&g_WihT[(size_t)(k0+brow)*G4_ + bn + bcol];
    __syncthreads();
    #pragma unroll
    for (int k = 0; k < BK; k++) {
      float a0 = As[k][ty*4+0], a1 = As[k][ty*4+1];
      float a2 = As[k][ty*4+2], a3 = As[k][ty*4+3];
      float b0 = Bs[k][tx*4+0], b1 = Bs[k][tx*4+1];
      float b2 = Bs[k][tx*4+2], b3 = Bs[k][tx*4+3];
      acc[0][0]+=a0*b0; acc[0][1]+=a0*b1; acc[0][2]+=a0*b2; acc[0][3]+=a0*b3;
      acc[1][0]+=a1*b0; acc[1][1]+=a1*b1; acc[1][2]+=a1*b2; acc[1][3]+=a1*b3;
      acc[2][0]+=a2*b0; acc[2][1]+=a2*b1; acc[2][2]+=a2*b2; acc[2][3]+=a2*b3;
      acc[3][0]+=a3*b0; acc[3][1]+=a3*b1; acc[3][2]+=a3*b2; acc[3][3]+=a3*b3;
    }
    __syncthreads();
  }
  #pragma unroll
  for (int i = 0; i < 4; i++) {
    int r = bm + ty*4 + i;
    int cc = bn + tx*4;
    float4 o;
    o.x = acc[i][0] + bias[cc+0];
    o.y = acc[i][1] + bias[cc+1];
    o.z = acc[i][2] + bias[cc+2];
    o.w = acc[i][3] + bias[cc+3];
    *(float4*)&g_xg[(size_t)r*G4_ + cc] = o;
  }
}

// ---------------- K2b: transpose xg (b,s,o) -> xgT (s,o,b) -------------------
__global__ __launch_bounds__(256) void xg_transpose_kernel() {
  __shared__ float tile[64][65];
  int o0 = blockIdx.x*64;
  int s  = blockIdx.y;
  int t  = threadIdx.x;
  int j  = t & 63, br = t >> 6;      // 4 row groups
  for (int bb = 0; bb < B_; bb += 4) {
    int b = bb + br;
    tile[b][j] = g_xg[((size_t)b*S_ + s)*G4_ + o0 + j];
  }
  __syncthreads();
  int bcol = t & 63, rr = t >> 6;
  for (int r4 = 0; r4 < 64; r4 += 4) {
    int r = r4 + rr;
    g_xgT[((size_t)s*G4_ + o0 + r)*B_ + bcol] = tile[bcol][r];
  }
}

// ---------------- K3: persistent 128-SM LSTM, weights smem-resident ----------
// CTA c owns gate rows {g*256 + 2c + p : g in 0..3, p in 0..1} (8 rows, 16KB
// duplicated-pair smem) and h-columns j = 2c, 2c+1. Each step: stage h (L2),
// [8x256]@[256x64] from smem, cell update (c-state in regs), write h to the
// other g_hT buffer, chip-wide barrier via per-step counters.
__global__ __launch_bounds__(256,1) void lstm3_kernel(const float* __restrict__ W_hh) {
  extern __shared__ float sm3[];
  float* hst = sm3;                                  // [256][64]  16384 f
  unsigned long long* Wsm2 =
      (unsigned long long*)(hst + H_*B_);            // [8][256] dup pairs 16KB
  float* psum = (float*)(Wsm2 + 8*H_);               // [2][8][64]

  int tid = threadIdx.x;             // 256
  int cta = blockIdx.x;              // 0..127

  // load 8 weight rows once, duplicated-pair packed
  for (int i = tid; i < 8*H_; i += 256) {
    int r = i >> 8, k = i & 255;
    int grow = (r >> 1)*H_ + 2*cta + (r & 1);        // global gate row
    float v = W_hh[(size_t)grow*H_ + k];
    float2 d = make_float2(v, v);
    Wsm2[i] = *(unsigned long long*)&d;
  }

  // compute-phase ids
  int l = tid & 31, w = tid >> 5;    // 8 warps
  int r0 = w & 3, r1 = (w & 3) + 4;
  int kh = w >> 2;                   // k-half
  // update-phase ids (tid < 128)
  int pr = tid >> 6;                 // 0/1 -> j = 2*cta + pr
  int ub = tid & 63;                 // batch
  float c = 0.f;
  __syncthreads();

  for (int s = 0; s < S_; s++) {
    int par = s & 1;
    // stage h[par] -> smem (fresh from L2)
    {
      const float4* src = (const float4*)(&g_hT[par][0][0]);
      float4* dst = (float4*)hst;
      #pragma unroll
      for (int i = 0; i < (H_*B_/4)/256; i++)
        dst[tid + i*256] = __ldcg(&src[tid + i*256]);
    }
    // prefetch xg gate inputs (independent loads, hidden under compute)
    float xgi=0.f, xgf=0.f, xgg=0.f, xgo=0.f;
    if (tid < 128) {
      size_t base = ((size_t)s*G4_ + 2*cta + pr)*B_ + ub;
      xgi = __ldg(&g_xgT[base]);
      xgf = __ldg(&g_xgT[base + (size_t)256*B_]);
      xgg = __ldg(&g_xgT[base + (size_t)512*B_]);
      xgo = __ldg(&g_xgT[base + (size_t)768*B_]);
    }
    __syncthreads();

    // gate GEMM: out[r][b] = sum_k W[r][k] * h[k][b], split over k-halves
    unsigned long long a0 = 0ULL, a1 = 0ULL;
    const unsigned long long* hp  = ((const unsigned long long*)hst) + l;
    const unsigned long long* w0p = Wsm2 + r0*H_;
    const unsigned long long* w1p = Wsm2 + r1*H_;
    #pragma unroll 4
    for (int k = kh*128; k < kh*128 + 128; k++) {
      unsigned long long h2 = hp[k*32];
      fma2(a0, w0p[k], h2);
      fma2(a1, w1p[k], h2);
    }
    ((unsigned long long*)psum)[(kh*8 + r0)*32 + l] = a0;
    ((unsigned long long*)psum)[(kh*8 + r1)*32 + l] = a1;
    __syncthreads();

    // cell update for j = 2*cta + pr, batch ub
    if (tid < 128) {
      float pi = psum[(0*2+pr)*64+ub] + psum[(8 + 0*2+pr)*64+ub] + xgi;
      float pf = psum[(1*2+pr)*64+ub] + psum[(8 + 1*2+pr)*64+ub] + xgf;
      float pg = psum[(2*2+pr)*64+ub] + psum[(8 + 2*2+pr)*64+ub] + xgg;
      float po = psum[(3*2+pr)*64+ub] + psum[(8 + 3*2+pr)*64+ub] + xgo;
      c = sigmf(pf)*c + sigmf(pi)*tanhf(pg);
      float h = sigmf(po)*tanhf(c);
      int j = 2*cta + pr;
      g_hout[((size_t)ub*S_ + s)*H_ + j] = h;
      g_hT[1-par][j][ub] = h;
    }
    __threadfence();
    __syncthreads();
    // chip-wide barrier: per-step arrival counter (all 128 CTAs resident)
    if (tid == 0) {
      int a = atomicAdd(&g_cnt[s], 1);
      if (a < NCTA-1) {
        while (*((volatile int*)&g_cnt[s]) < NCTA) { }
      }
    }
    __syncthreads();
  }
}

// ---------------- K4: masked attention pooling + logits ----------------------
__global__ __launch_bounds__(256) void attend_kernel(
    const int*   __restrict__ lengths,
    const float* __restrict__ attn_w,
    const float* __restrict__ attn_b,
    const float* __restrict__ out_w,
    const float* __restrict__ out_b,
    float*       __restrict__ out) {
  __shared__ float sw[H_];
  __shared__ float sc[S_];
  __shared__ float smax, sinv;
  __shared__ float lg[3];
  int tid = threadIdx.x;
  int b = blockIdx.x;
  const float* ho = g_hout + (size_t)b*S_*H_;

  sw[tid] = attn_w[tid];
  if (tid < 3) lg[tid] = 0.f;
  __syncthreads();

  int lane = tid & 31, wid = tid >> 5;  // 8 warps
  float ab = attn_b[0];
  for (int s = wid; s < S_; s += 8) {
    float p = 0.f;
    for (int k = lane; k < H_; k += 32) p += ho[(size_t)s*H_ + k]*sw[k];
    #pragma unroll
    for (int off = 16; off; off >>= 1) p += __shfl_down_sync(0xffffffffu, p, off);
    if (lane == 0) sc[s] = p + ab;
  }
  __syncthreads();

  int len = lengths[b];
  if (tid == 0) {
    float m = -1e30f;
    for (int s = 0; s < len; s++) m = fmaxf(m, sc[s]);
    smax = m;
  }
  __syncthreads();
  if (tid < S_) sc[tid] = (tid < len) ? expf(sc[tid]-smax) : 0.f;
  __syncthreads();
  if (tid == 0) {
    float sum = 0.f;
    for (int s = 0; s < S_; s++) sum += sc[s];
    sinv = 1.f/sum;
  }
  __syncthreads();

  float att = 0.f;
  for (int s = 0; s < S_; s++) att += sc[s]*ho[(size_t)s*H_ + tid];
  att *= sinv;
  #pragma unroll
  for (int c = 0; c < 3; c++) atomicAdd(&lg[c], att*out_w[c*H_ + tid]);
  __syncthreads();
  if (tid < 3) out[b*3 + tid] = lg[tid] + out_b[tid];
}

// ---------------- launcher ---------------------------------------------------
extern "C" void kernel_launch(void* const* d_in, const int* in_sizes, int n_in,
                              void* d_out, int out_size) {
  const int*   inputs  = (const int*)  d_in[0];
  // d_in[1] = context (unused by the reference)
  const int*   triples = (const int*)  d_in[2];
  const int*   lengths = (const int*)  d_in[3];
  const int*   id2     = (const int*)  d_in[4];
  const float* emb     = (const float*)d_in[5];
  const float* ent     = (const float*)d_in[6];
  const float* rel     = (const float*)d_in[7];
  const float* W_ent   = (const float*)d_in[8];
  const float* W_ih    = (const float*)d_in[9];
  const float* W_hh    = (const float*)d_in[10];
  const float* b_lstm  = (const float*)d_in[11];
  const float* attn_w  = (const float*)d_in[12];
  const float* attn_b  = (const float*)d_in[13];
  const float* out_w   = (const float*)d_in[14];
  const float* out_b   = (const float*)d_in[15];
  float* out = (float*)d_out;

  prep_kernel<<<(KP_*G4_+255)/256, 256>>>(W_ih);

  size_t sm1 = (size_t)(200*WTS + T_*200 + T_*D_) * sizeof(float);  // ~92.8 KB
  cudaFuncSetAttribute(graph_tin_kernel,
                       cudaFuncAttributeMaxDynamicSharedMemorySize, (int)sm1);
  graph_tin_kernel<<<NTOK/TOKB, 256, sm1>>>(inputs, triples, id2,
                                            emb, ent, rel, W_ent);

  dim3 g2(G4_/BN, NTOK/BM);
  gemm_xg_kernel<<<g2, 256>>>(b_lstm);

  xg_transpose_kernel<<<dim3(G4_/64, S_), 256>>>();

  size_t sm3 = (size_t)(H_*B_)*sizeof(float)        // h stage 64KB
             + (size_t)(8*H_)*sizeof(unsigned long long)  // W pairs 16KB
             + (size_t)(2*8*64)*sizeof(float);      // psum 4KB
  cudaFuncSetAttribute(lstm3_kernel,
                       cudaFuncAttributeMaxDynamicSharedMemorySize, (int)sm3);
  lstm3_kernel<<<NCTA, 256, sm3>>>(W_hh);

  attend_kernel<<<B_, 256>>>(lengths, attn_w, attn_b, out_w, out_b, out);
}

// round 14
// speedup vs baseline: 2.1459x; 1.0465x over previous
#include <cuda_runtime.h>
#include <math.h>
#include <stdint.h>

// Problem constants
#define B_   64
#define S_   128
#define T_   10
#define E_   300
#define D_   100
#define H_   256
#define IN_  500
#define KP_  512          // padded K for the big GEMM
#define G4_  1024         // 4*H
#define NTOK (B_*S_)      // 8192
#define NCTA 128          // persistent LSTM CTAs

// ---------------- scratch (static device globals; no runtime alloc) ----------
__device__ float g_WihT[KP_*G4_];           // [512][1024] (zero-padded rows >= 500)
__device__ float g_tin[(size_t)NTOK*KP_];   // [8192][512]
__device__ float g_xg[(size_t)NTOK*G4_];    // [8192][1024]  (b,s,o)
__device__ float g_xgT[(size_t)S_*G4_*B_];  // [128][1024][64] (s,o,b)
__device__ float g_hout[(size_t)NTOK*H_];   // [64][128][256]
__device__ float g_hT[2][H_][B_];           // double-buffered h, transposed [k][b]
__device__ int   g_cnt[S_];                 // per-step arrival counters

__device__ __forceinline__ float sigmf(float x) { return 1.f/(1.f+expf(-x)); }

// packed fp32x2 FMA: acc += a*b elementwise on two packed fp32 lanes
__device__ __forceinline__ void fma2(unsigned long long& acc,
                                     unsigned long long a,
                                     unsigned long long b) {
  asm("fma.rn.f32x2 %0, %1, %2, %0;" : "+l"(acc) : "l"(a), "l"(b));
}

// ---------------- prep: transpose W_ih; zero hT buf0 + step counters ---------
__global__ void prep_kernel(const float* __restrict__ W_ih) {
  int idx = blockIdx.x*256 + threadIdx.x;
  if (idx < KP_*G4_) {
    int k = idx >> 10, o = idx & 1023;
    g_WihT[idx] = (k < IN_) ? W_ih[o*IN_ + k] : 0.f;
  }
  if (idx < H_*B_) ((float*)g_hT)[idx] = 0.f;   // buffer 0 only
  if (idx < S_)    g_cnt[idx] = 0;
}

// ---------------- K1: graph attention + t_in assembly ------------------------
#define TOKB 8
#define WTS  101   // padded stride for W_ent^T in smem (conflict-free)

__global__ void graph_tin_kernel(const int* __restrict__ inputs,
                                 const int* __restrict__ triples,
                                 const int* __restrict__ id2,
                                 const float* __restrict__ emb,
                                 const float* __restrict__ ent,
                                 const float* __restrict__ rel,
                                 const float* __restrict__ W_ent) {
  extern __shared__ float sm[];
  float* Wt = sm;                   // [200][101]
  float* ht = Wt + 200*WTS;         // [10][200]
  float* er = ht + T_*200;          // [10][100]
  __shared__ float ev[T_];
  __shared__ float alpha[T_];
  __shared__ int   s_valid;
  int tid = threadIdx.x;            // 256 threads

  for (int idx = tid; idx < D_*2*D_; idx += 256) {
    int d = idx / 200, k = idx % 200;
    Wt[k*WTS + d] = W_ent[idx];
  }
  __syncthreads();

  for (int tt = 0; tt < TOKB; tt++) {
    int tok = blockIdx.x*TOKB + tt;
    const int* tri = triples + tok*T_*3;

    for (int idx = tid; idx < T_*200; idx += 256) {
      int t = idx / 200, j = idx % 200;
      int r  = (j < D_) ? tri[t*3] : tri[t*3+1];
      int jj = (j < D_) ? j : j - D_;
      ht[idx] = ent[(size_t)r*D_ + jj];
    }
    for (int idx = tid; idx < T_*D_; idx += 256) {
      int t = idx / D_, j = idx % D_;
      er[idx] = rel[(size_t)tri[t*3+2]*D_ + j];
    }
    if (tid < T_) ev[tid] = 0.f;
    if (tid == 0) {
      int v = 0;
      for (int t = 0; t < T_; t++) v |= (id2[tok*T_+t] != -1);
      s_valid = v;
    }
    __syncthreads();

    if (tid < 200) {
      int d  = tid % D_;
      int tg = tid / D_;
      const float* h0 = ht + (tg*5+0)*200;
      const float* h1 = ht + (tg*5+1)*200;
      const float* h2 = ht + (tg*5+2)*200;
      const float* h3 = ht + (tg*5+3)*200;
      const float* h4 = ht + (tg*5+4)*200;
      float a0=0.f,a1=0.f,a2=0.f,a3=0.f,a4=0.f;
      for (int k = 0; k < 200; k += 4) {
        float4 v0 = *(const float4*)(h0+k);
        float4 v1 = *(const float4*)(h1+k);
        float4 v2 = *(const float4*)(h2+k);
        float4 v3 = *(const float4*)(h3+k);
        float4 v4 = *(const float4*)(h4+k);
        float w0 = Wt[(k+0)*WTS+d];
        float w1 = Wt[(k+1)*WTS+d];
        float w2 = Wt[(k+2)*WTS+d];
        float w3 = Wt[(k+3)*WTS+d];
        a0 += w0*v0.x + w1*v0.y + w2*v0.z + w3*v0.w;
        a1 += w0*v1.x + w1*v1.y + w2*v1.z + w3*v1.w;
        a2 += w0*v2.x + w1*v2.y + w2*v2.z + w3*v2.w;
        a3 += w0*v3.x + w1*v3.y + w2*v3.z + w3*v3.w;
        a4 += w0*v4.x + w1*v4.y + w2*v4.z + w3*v4.w;
      }
      atomicAdd(&ev[tg*5+0], tanhf(a0)*er[(tg*5+0)*D_+d]);
      atomicAdd(&ev[tg*5+1], tanhf(a1)*er[(tg*5+1)*D_+d]);
      atomicAdd(&ev[tg*5+2], tanhf(a2)*er[(tg*5+2)*D_+d]);
      atomicAdd(&ev[tg*5+3], tanhf(a3)*er[(tg*5+3)*D_+d]);
      atomicAdd(&ev[tg*5+4], tanhf(a4)*er[(tg*5+4)*D_+d]);
    }
    __syncthreads();

    if (tid == 0) {
      float mx = ev[0];
      for (int t = 1; t < T_; t++) mx = fmaxf(mx, ev[t]);
      float sum = 0.f;
      for (int t = 0; t < T_; t++) { float e = expf(ev[t]-mx); alpha[t]=e; sum+=e; }
      float inv = 1.f/sum;
      for (int t = 0; t < T_; t++) alpha[t] *= inv;
    }
    __syncthreads();

    float* row = g_tin + (size_t)tok*KP_;
    const float* xr = emb + (size_t)inputs[tok]*E_;
    for (int j = tid; j < E_; j += 256) row[j] = xr[j];
    float vm = s_valid ? 1.f : 0.f;
    for (int j = tid; j < 200; j += 256) {
      float g = 0.f;
      #pragma unroll
      for (int t = 0; t < T_; t++) g += alpha[t]*ht[t*200+j];
      row[E_+j] = g*vm;
    }
    if (tid < KP_-IN_) row[IN_+tid] = 0.f;
    __syncthreads();
  }
}

// ---------------- K2: xg = t_in @ W_ih^T + b  (SGEMM 8192x1024x512) ----------
#define BM 64
#define BN 64
#define BK 16

__global__ __launch_bounds__(256) void gemm_xg_kernel(const float* __restrict__ bias) {
  __shared__ float As[BK][BM+4];
  __shared__ float Bs[BK][BN];
  int tid = threadIdx.x;
  int tx = tid & 15, ty = tid >> 4;
  int bm = blockIdx.y * BM, bn = blockIdx.x * BN;
  int arow = tid >> 2, acol = (tid & 3) << 2;
  int brow = tid >> 4, bcol = (tid & 15) << 2;
  const float* Ab = g_tin + (size_t)bm*KP_;
  float acc[4][4] = {};
  for (int k0 = 0; k0 < KP_; k0 += BK) {
    float4 av = *(const float4*)&Ab[(size_t)arow*KP_ + k0 + acol];
    As[acol+0][arow]=av.x; As[acol+1][arow]=av.y;
    As[acol+2][arow]=av.z; As[acol+3][arow]=av.w;
    *(float4*)&Bs[brow][bcol] = *(const float4*)&g_WihT[(size_t)(k0+brow)*G4_ + bn + bcol];
    __syncthreads();
    #pragma unroll
    for (int k = 0; k < BK; k++) {
      float a0 = As[k][ty*4+0], a1 = As[k][ty*4+1];
      float a2 = As[k][ty*4+2], a3 = As[k][ty*4+3];
      float b0 = Bs[k][tx*4+0], b1 = Bs[k][tx*4+1];
      float b2 = Bs[k][tx*4+2], b3 = Bs[k][tx*4+3];
      acc[0][0]+=a0*b0; acc[0][1]+=a0*b1; acc[0][2]+=a0*b2; acc[0][3]+=a0*b3;
      acc[1][0]+=a1*b0; acc[1][1]+=a1*b1; acc[1][2]+=a1*b2; acc[1][3]+=a1*b3;
      acc[2][0]+=a2*b0; acc[2][1]+=a2*b1; acc[2][2]+=a2*b2; acc[2][3]+=a2*b3;
      acc[3][0]+=a3*b0; acc[3][1]+=a3*b1; acc[3][2]+=a3*b2; acc[3][3]+=a3*b3;
    }
    __syncthreads();
  }
  #pragma unroll
  for (int i = 0; i < 4; i++) {
    int r = bm + ty*4 + i;
    int cc = bn + tx*4;
    float4 o;
    o.x = acc[i][0] + bias[cc+0];
    o.y = acc[i][1] + bias[cc+1];
    o.z = acc[i][2] + bias[cc+2];
    o.w = acc[i][3] + bias[cc+3];
    *(float4*)&g_xg[(size_t)r*G4_ + cc] = o;
  }
}

// ---------------- K2b: transpose xg (b,s,o) -> xgT (s,o,b) -------------------
__global__ __launch_bounds__(256) void xg_transpose_kernel() {
  __shared__ float tile[64][65];
  int o0 = blockIdx.x*64;
  int s  = blockIdx.y;
  int t  = threadIdx.x;
  int j  = t & 63, br = t >> 6;      // 4 row groups
  for (int bb = 0; bb < B_; bb += 4) {
    int b = bb + br;
    tile[b][j] = g_xg[((size_t)b*S_ + s)*G4_ + o0 + j];
  }
  __syncthreads();
  int bcol = t & 63, rr = t >> 6;
  for (int r4 = 0; r4 < 64; r4 += 4) {
    int r = r4 + rr;
    g_xgT[((size_t)s*G4_ + o0 + r)*B_ + bcol] = tile[bcol][r];
  }
}

// ---------------- K3: persistent 128-SM LSTM, weights smem-resident ----------
// CTA c owns gate rows {g*256 + 2c + p : g in 0..3, p in 0..1} (8 rows) and
// h-columns j = 2c, 2c+1. Weights repacked Wq[k][r] (duplicated pairs) so each
// warp covers ALL 8 rows over one k-eighth: per k, one h LDS.64 (h crosses the
// crossbar exactly once per step) + 4 LDS.128 broadcasts fetch all 8 w rows.
__global__ __launch_bounds__(256,1) void lstm4_kernel(const float* __restrict__ W_hh) {
  extern __shared__ float sm3[];
  float* hst = sm3;                                  // [256][64]   64 KB
  unsigned long long* Wq =
      (unsigned long long*)(hst + H_*B_);            // [256][8] dup pairs 16 KB
  float* psum = (float*)(Wq + H_*8);                 // [8][8][64]  16 KB

  int tid = threadIdx.x;             // 256
  int cta = blockIdx.x;              // 0..127

  // load 8 weight rows once: Wq[k][r] = (w,w) for global row (r>>1)*256+2c+(r&1)
  for (int i = tid; i < 8*H_; i += 256) {
    int k = i >> 3, r = i & 7;
    int grow = (r >> 1)*H_ + 2*cta + (r & 1);
    float v = W_hh[(size_t)grow*H_ + k];
    float2 d = make_float2(v, v);
    Wq[i] = *(unsigned long long*)&d;                // i == k*8 + r
  }

  // compute-phase ids: warp kp owns k-eighth [kp*32, kp*32+32)
  int l  = tid & 31;
  int kp = tid >> 5;                 // 8 warps
  // update-phase ids (tid < 128)
  int pr = tid >> 6;                 // 0/1 -> j = 2*cta + pr
  int ub = tid & 63;                 // batch
  float c = 0.f;
  __syncthreads();

  const unsigned long long* hp = ((const unsigned long long*)hst) + l;
  const ulonglong2* wq2 = (const ulonglong2*)Wq;     // [256][4]

  for (int s = 0; s < S_; s++) {
    int par = s & 1;
    // stage h[par] -> smem (fresh from L2)
    {
      const float4* src = (const float4*)(&g_hT[par][0][0]);
      float4* dst = (float4*)hst;
      #pragma unroll
      for (int i = 0; i < (H_*B_/4)/256; i++)
        dst[tid + i*256] = __ldcg(&src[tid + i*256]);
    }
    // prefetch xg gate inputs (independent loads, hidden under compute)
    float xgi=0.f, xgf=0.f, xgg=0.f, xgo=0.f;
    if (tid < 128) {
      size_t base = ((size_t)s*G4_ + 2*cta + pr)*B_ + ub;
      xgi = __ldg(&g_xgT[base]);
      xgf = __ldg(&g_xgT[base + (size_t)256*B_]);
      xgg = __ldg(&g_xgT[base + (size_t)512*B_]);
      xgo = __ldg(&g_xgT[base + (size_t)768*B_]);
    }
    __syncthreads();

    // gate GEMM: acc[r] (b-pair l) += sum_{k in eighth} w[r][k] * h[k][2l..2l+1]
    unsigned long long acc0=0ULL, acc1=0ULL, acc2=0ULL, acc3=0ULL;
    unsigned long long acc4=0ULL, acc5=0ULL, acc6=0ULL, acc7=0ULL;
    #pragma unroll 8
    for (int k = kp*32; k < kp*32 + 32; k++) {
      unsigned long long h2 = hp[k*32];
      ulonglong2 w01 = wq2[k*4 + 0];
      ulonglong2 w23 = wq2[k*4 + 1];
      ulonglong2 w45 = wq2[k*4 + 2];
      ulonglong2 w67 = wq2[k*4 + 3];
      fma2(acc0, w01.x, h2); fma2(acc1, w01.y, h2);
      fma2(acc2, w23.x, h2); fma2(acc3, w23.y, h2);
      fma2(acc4, w45.x, h2); fma2(acc5, w45.y, h2);
      fma2(acc6, w67.x, h2); fma2(acc7, w67.y, h2);
    }
    {
      unsigned long long* pp = ((unsigned long long*)psum) + kp*8*32 + l;
      pp[0*32] = acc0; pp[1*32] = acc1; pp[2*32] = acc2; pp[3*32] = acc3;
      pp[4*32] = acc4; pp[5*32] = acc5; pp[6*32] = acc6; pp[7*32] = acc7;
    }
    __syncthreads();

    // cell update for j = 2*cta + pr, batch ub (8-part k reduction)
    if (tid < 128) {
      float pre[4];
      #pragma unroll
      for (int g = 0; g < 4; g++) {
        int r = g*2 + pr;
        float sum = 0.f;
        #pragma unroll
        for (int kq = 0; kq < 8; kq++)
          sum += psum[(kq*8 + r)*64 + ub];
        pre[g] = sum;
      }
      pre[0] += xgi; pre[1] += xgf; pre[2] += xgg; pre[3] += xgo;
      c = sigmf(pre[1])*c + sigmf(pre[0])*tanhf(pre[2]);
      float h = sigmf(pre[3])*tanhf(c);
      int j = 2*cta + pr;
      g_hout[((size_t)ub*S_ + s)*H_ + j] = h;
      g_hT[1-par][j][ub] = h;
    }
    __threadfence();
    __syncthreads();
    // chip-wide barrier: per-step arrival counter (all 128 CTAs resident)
    if (tid == 0) {
      int a = atomicAdd(&g_cnt[s], 1);
      if (a < NCTA-1) {
        while (*((volatile int*)&g_cnt[s]) < NCTA) { }
      }
    }
    __syncthreads();
  }
}

// ---------------- K4: masked attention pooling + logits ----------------------
__global__ __launch_bounds__(256) void attend_kernel(
    const int*   __restrict__ lengths,
    const float* __restrict__ attn_w,
    const float* __restrict__ attn_b,
    const float* __restrict__ out_w,
    const float* __restrict__ out_b,
    float*       __restrict__ out) {
  __shared__ float sw[H_];
  __shared__ float sc[S_];
  __shared__ float smax, sinv;
  __shared__ float lg[3];
  int tid = threadIdx.x;
  int b = blockIdx.x;
  const float* ho = g_hout + (size_t)b*S_*H_;

  sw[tid] = attn_w[tid];
  if (tid < 3) lg[tid] = 0.f;
  __syncthreads();

  int lane = tid & 31, wid = tid >> 5;  // 8 warps
  float ab = attn_b[0];
  for (int s = wid; s < S_; s += 8) {
    float p = 0.f;
    for (int k = lane; k < H_; k += 32) p += ho[(size_t)s*H_ + k]*sw[k];
    #pragma unroll
    for (int off = 16; off; off >>= 1) p += __shfl_down_sync(0xffffffffu, p, off);
    if (lane == 0) sc[s] = p + ab;
  }
  __syncthreads();

  int len = lengths[b];
  if (tid == 0) {
    float m = -1e30f;
    for (int s = 0; s < len; s++) m = fmaxf(m, sc[s]);
    smax = m;
  }
  __syncthreads();
  if (tid < S_) sc[tid] = (tid < len) ? expf(sc[tid]-smax) : 0.f;
  __syncthreads();
  if (tid == 0) {
    float sum = 0.f;
    for (int s = 0; s < S_; s++) sum += sc[s];
    sinv = 1.f/sum;
  }
  __syncthreads();

  float att = 0.f;
  for (int s = 0; s < S_; s++) att += sc[s]*ho[(size_t)s*H_ + tid];
  att *= sinv;
  #pragma unroll
  for (int c = 0; c < 3; c++) atomicAdd(&lg[c], att*out_w[c*H_ + tid]);
  __syncthreads();
  if (tid < 3) out[b*3 + tid] = lg[tid] + out_b[tid];
}

// ---------------- launcher ---------------------------------------------------
extern "C" void kernel_launch(void* const* d_in, const int* in_sizes, int n_in,
                              void* d_out, int out_size) {
  const int*   inputs  = (const int*)  d_in[0];
  // d_in[1] = context (unused by the reference)
  const int*   triples = (const int*)  d_in[2];
  const int*   lengths = (const int*)  d_in[3];
  const int*   id2     = (const int*)  d_in[4];
  const float* emb     = (const float*)d_in[5];
  const float* ent     = (const float*)d_in[6];
  const float* rel     = (const float*)d_in[7];
  const float* W_ent   = (const float*)d_in[8];
  const float* W_ih    = (const float*)d_in[9];
  const float* W_hh    = (const float*)d_in[10];
  const float* b_lstm  = (const float*)d_in[11];
  const float* attn_w  = (const float*)d_in[12];
  const float* attn_b  = (const float*)d_in[13];
  const float* out_w   = (const float*)d_in[14];
  const float* out_b   = (const float*)d_in[15];
  float* out = (float*)d_out;

  prep_kernel<<<(KP_*G4_+255)/256, 256>>>(W_ih);

  size_t sm1 = (size_t)(200*WTS + T_*200 + T_*D_) * sizeof(float);  // ~92.8 KB
  cudaFuncSetAttribute(graph_tin_kernel,
                       cudaFuncAttributeMaxDynamicSharedMemorySize, (int)sm1);
  graph_tin_kernel<<<NTOK/TOKB, 256, sm1>>>(inputs, triples, id2,
                                            emb, ent, rel, W_ent);

  dim3 g2(G4_/BN, NTOK/BM);
  gemm_xg_kernel<<<g2, 256>>>(b_lstm);

  xg_transpose_kernel<<<dim3(G4_/64, S_), 256>>>();

  size_t sm3 = (size_t)(H_*B_)*sizeof(float)              // h stage 64KB
             + (size_t)(8*H_)*sizeof(unsigned long long)  // Wq pairs 16KB
             + (size_t)(8*8*64)*sizeof(float);            // psum 16KB
  cudaFuncSetAttribute(lstm4_kernel,
                       cudaFuncAttributeMaxDynamicSharedMemorySize, (int)sm3);
  lstm4_kernel<<<NCTA, 256, sm3>>>(W_hh);

  attend_kernel<<<B_, 256>>>(lengths, attn_w, attn_b, out_w, out_b, out);
}

// round 15
// speedup vs baseline: 2.2643x; 1.0551x over previous
#include <cuda_runtime.h>
#include <math.h>
#include <stdint.h>

// Problem constants
#define B_   64
#define S_   128
#define T_   10
#define E_   300
#define D_   100
#define H_   256
#define IN_  500
#define KP_  512          // padded K for the big GEMM
#define G4_  1024         // 4*H
#define NTOK (B_*S_)      // 8192
#define NCTA 128          // persistent LSTM CTAs
#define FSTR 32           // flag stride in ints (128B lines)

// ---------------- scratch (static device globals; no runtime alloc) ----------
__device__ float g_WihT[KP_*G4_];           // [512][1024] (zero-padded rows >= 500)
__device__ float g_tin[(size_t)NTOK*KP_];   // [8192][512]
__device__ float g_xg[(size_t)NTOK*G4_];    // [8192][1024]  (b,s,o)
__device__ float g_xgT[(size_t)S_*G4_*B_];  // [128][1024][64] (s,o,b)
__device__ float g_hout[(size_t)NTOK*H_];   // [64][128][256]  (b,s,h) for attend
__device__ float g_houtT[(size_t)S_*H_*B_]; // [128][256][64]  (s,h,b) LSTM output
__device__ float g_hT[2][H_][B_];           // double-buffered h, transposed [k][b]
__device__ int   g_flag[NCTA*FSTR];         // per-CTA monotonic step flags

__device__ __forceinline__ float sigmf(float x) { return 1.f/(1.f+expf(-x)); }

// packed fp32x2 FMA: acc += a*b elementwise on two packed fp32 lanes
__device__ __forceinline__ void fma2(unsigned long long& acc,
                                     unsigned long long a,
                                     unsigned long long b) {
  asm("fma.rn.f32x2 %0, %1, %2, %0;" : "+l"(acc) : "l"(a), "l"(b));
}
__device__ __forceinline__ int ld_acquire(const int* p) {
  int v;
  asm volatile("ld.acquire.gpu.global.b32 %0, [%1];" : "=r"(v) : "l"(p) : "memory");
  return v;
}
__device__ __forceinline__ void st_release(int* p, int v) {
  asm volatile("st.release.gpu.global.b32 [%0], %1;" :: "l"(p), "r"(v) : "memory");
}

// ---------------- prep: transpose W_ih; zero hT buf0 + flags -----------------
__global__ void prep_kernel(const float* __restrict__ W_ih) {
  int idx = blockIdx.x*256 + threadIdx.x;
  if (idx < KP_*G4_) {
    int k = idx >> 10, o = idx & 1023;
    g_WihT[idx] = (k < IN_) ? W_ih[o*IN_ + k] : 0.f;
  }
  if (idx < H_*B_) ((float*)g_hT)[idx] = 0.f;   // buffer 0 only
  if (idx < NCTA*FSTR) g_flag[idx] = 0;
}

// ---------------- K1: graph attention + t_in assembly ------------------------
#define TOKB 8
#define WTS  101   // padded stride for W_ent^T in smem (conflict-free)

__global__ void graph_tin_kernel(const int* __restrict__ inputs,
                                 const int* __restrict__ triples,
                                 const int* __restrict__ id2,
                                 const float* __restrict__ emb,
                                 const float* __restrict__ ent,
                                 const float* __restrict__ rel,
                                 const float* __restrict__ W_ent) {
  extern __shared__ float sm[];
  float* Wt = sm;                   // [200][101]
  float* ht = Wt + 200*WTS;         // [10][200]
  float* er = ht + T_*200;          // [10][100]
  __shared__ float ev[T_];
  __shared__ float alpha[T_];
  __shared__ int   s_valid;
  int tid = threadIdx.x;            // 256 threads

  for (int idx = tid; idx < D_*2*D_; idx += 256) {
    int d = idx / 200, k = idx % 200;
    Wt[k*WTS + d] = W_ent[idx];
  }
  __syncthreads();

  for (int tt = 0; tt < TOKB; tt++) {
    int tok = blockIdx.x*TOKB + tt;
    const int* tri = triples + tok*T_*3;

    for (int idx = tid; idx < T_*200; idx += 256) {
      int t = idx / 200, j = idx % 200;
      int r  = (j < D_) ? tri[t*3] : tri[t*3+1];
      int jj = (j < D_) ? j : j - D_;
      ht[idx] = ent[(size_t)r*D_ + jj];
    }
    for (int idx = tid; idx < T_*D_; idx += 256) {
      int t = idx / D_, j = idx % D_;
      er[idx] = rel[(size_t)tri[t*3+2]*D_ + j];
    }
    if (tid < T_) ev[tid] = 0.f;
    if (tid == 0) {
      int v = 0;
      for (int t = 0; t < T_; t++) v |= (id2[tok*T_+t] != -1);
      s_valid = v;
    }
    __syncthreads();

    if (tid < 200) {
      int d  = tid % D_;
      int tg = tid / D_;
      const float* h0 = ht + (tg*5+0)*200;
      const float* h1 = ht + (tg*5+1)*200;
      const float* h2 = ht + (tg*5+2)*200;
      const float* h3 = ht + (tg*5+3)*200;
      const float* h4 = ht + (tg*5+4)*200;
      float a0=0.f,a1=0.f,a2=0.f,a3=0.f,a4=0.f;
      for (int k = 0; k < 200; k += 4) {
        float4 v0 = *(const float4*)(h0+k);
        float4 v1 = *(const float4*)(h1+k);
        float4 v2 = *(const float4*)(h2+k);
        float4 v3 = *(const float4*)(h3+k);
        float4 v4 = *(const float4*)(h4+k);
        float w0 = Wt[(k+0)*WTS+d];
        float w1 = Wt[(k+1)*WTS+d];
        float w2 = Wt[(k+2)*WTS+d];
        float w3 = Wt[(k+3)*WTS+d];
        a0 += w0*v0.x + w1*v0.y + w2*v0.z + w3*v0.w;
        a1 += w0*v1.x + w1*v1.y + w2*v1.z + w3*v1.w;
        a2 += w0*v2.x + w1*v2.y + w2*v2.z + w3*v2.w;
        a3 += w0*v3.x + w1*v3.y + w2*v3.z + w3*v3.w;
        a4 += w0*v4.x + w1*v4.y + w2*v4.z + w3*v4.w;
      }
      atomicAdd(&ev[tg*5+0], tanhf(a0)*er[(tg*5+0)*D_+d]);
      atomicAdd(&ev[tg*5+1], tanhf(a1)*er[(tg*5+1)*D_+d]);
      atomicAdd(&ev[tg*5+2], tanhf(a2)*er[(tg*5+2)*D_+d]);
      atomicAdd(&ev[tg*5+3], tanhf(a3)*er[(tg*5+3)*D_+d]);
      atomicAdd(&ev[tg*5+4], tanhf(a4)*er[(tg*5+4)*D_+d]);
    }
    __syncthreads();

    if (tid == 0) {
      float mx = ev[0];
      for (int t = 1; t < T_; t++) mx = fmaxf(mx, ev[t]);
      float sum = 0.f;
      for (int t = 0; t < T_; t++) { float e = expf(ev[t]-mx); alpha[t]=e; sum+=e; }
      float inv = 1.f/sum;
      for (int t = 0; t < T_; t++) alpha[t] *= inv;
    }
    __syncthreads();

    float* row = g_tin + (size_t)tok*KP_;
    const float* xr = emb + (size_t)inputs[tok]*E_;
    for (int j = tid; j < E_; j += 256) row[j] = xr[j];
    float vm = s_valid ? 1.f : 0.f;
    for (int j = tid; j < 200; j += 256) {
      float g = 0.f;
      #pragma unroll
      for (int t = 0; t < T_; t++) g += alpha[t]*ht[t*200+j];
      row[E_+j] = g*vm;
    }
    if (tid < KP_-IN_) row[IN_+tid] = 0.f;
    __syncthreads();
  }
}

// ---------------- K2: xg = t_in @ W_ih^T + b  (SGEMM 8192x1024x512) ----------
#define BM 64
#define BN 64
#define BK 16

__global__ __launch_bounds__(256) void gemm_xg_kernel(const float* __restrict__ bias) {
  __shared__ float As[BK][BM+4];
  __shared__ float Bs[BK][BN];
  int tid = threadIdx.x;
  int tx = tid & 15, ty = tid >> 4;
  int bm = blockIdx.y * BM, bn = blockIdx.x * BN;
  int arow = tid >> 2, acol = (tid & 3) << 2;
  int brow = tid >> 4, bcol = (tid & 15) << 2;
  const float* Ab = g_tin + (size_t)bm*KP_;
  float acc[4][4] = {};
  for (int k0 = 0; k0 < KP_; k0 += BK) {
    float4 av = *(const float4*)&Ab[(size_t)arow*KP_ + k0 + acol];
    As[acol+0][arow]=av.x; As[acol+1][arow]=av.y;
    As[acol+2][arow]=av.z; As[acol+3][arow]=av.w;
    *(float4*)&Bs[brow][bcol] = *(const float4*)&g_WihT[(size_t)(k0+brow)*G4_ + bn + bcol];
    __syncthreads();
    #pragma unroll
    for (int k = 0; k < BK; k++) {
      float a0 = As[k][ty*4+0], a1 = As[k][ty*4+1];
      float a2 = As[k][ty*4+2], a3 = As[k][ty*4+3];
      float b0 = Bs[k][tx*4+0], b1 = Bs[k][tx*4+1];
      float b2 = Bs[k][tx*4+2], b3 = Bs[k][tx*4+3];
      acc[0][0]+=a0*b0; acc[0][1]+=a0*b1; acc[0][2]+=a0*b2; acc[0][3]+=a0*b3;
      acc[1][0]+=a1*b0; acc[1][1]+=a1*b1; acc[1][2]+=a1*b2; acc[1][3]+=a1*b3;
      acc[2][0]+=a2*b0; acc[2][1]+=a2*b1; acc[2][2]+=a2*b2; acc[2][3]+=a2*b3;
      acc[3][0]+=a3*b0; acc[3][1]+=a3*b1; acc[3][2]+=a3*b2; acc[3][3]+=a3*b3;
    }
    __syncthreads();
  }
  #pragma unroll
  for (int i = 0; i < 4; i++) {
    int r = bm + ty*4 + i;
    int cc = bn + tx*4;
    float4 o;
    o.x = acc[i][0] + bias[cc+0];
    o.y = acc[i][1] + bias[cc+1];
    o.z = acc[i][2] + bias[cc+2];
    o.w = acc[i][3] + bias[cc+3];
    *(float4*)&g_xg[(size_t)r*G4_ + cc] = o;
  }
}

// ---------------- K2b: transpose xg (b,s,o) -> xgT (s,o,b) -------------------
__global__ __launch_bounds__(256) void xg_transpose_kernel() {
  __shared__ float tile[64][65];
  int o0 = blockIdx.x*64;
  int s  = blockIdx.y;
  int t  = threadIdx.x;
  int j  = t & 63, br = t >> 6;      // 4 row groups
  for (int bb = 0; bb < B_; bb += 4) {
    int b = bb + br;
    tile[b][j] = g_xg[((size_t)b*S_ + s)*G4_ + o0 + j];
  }
  __syncthreads();
  int bcol = t & 63, rr = t >> 6;
  for (int r4 = 0; r4 < 64; r4 += 4) {
    int r = r4 + rr;
    g_xgT[((size_t)s*G4_ + o0 + r)*B_ + bcol] = tile[bcol][r];
  }
}

// ---------------- K3: persistent 128-SM LSTM, dataflow flag sync -------------
// CTA c owns gate rows {g*256 + 2c + p} (8 rows in smem, Wq[k][r] dup-pairs)
// and h-columns j = 2c, 2c+1. No global barrier: CTA c publishes flag=s+1
// (st.release) after writing h(s); warp kp polls only its 16 producer CTAs
// (ld.acquire) and loads its h slice straight from L2 (__ldcg).
__global__ __launch_bounds__(256,1) void lstm5_kernel(const float* __restrict__ W_hh) {
  __shared__ unsigned long long Wq[8*H_];  // [256][8] dup pairs, 16 KB
  __shared__ float psum[8*8*64];           // [kq][r][b], 16 KB

  int tid = threadIdx.x;             // 256
  int cta = blockIdx.x;              // 0..127

  // load 8 weight rows once: Wq[k*8+r] = (w,w) for global row (r>>1)*256+2c+(r&1)
  for (int i = tid; i < 8*H_; i += 256) {
    int k = i >> 3, r = i & 7;
    int grow = (r >> 1)*H_ + 2*cta + (r & 1);
    float v = W_hh[(size_t)grow*H_ + k];
    float2 d = make_float2(v, v);
    Wq[i] = *(unsigned long long*)&d;
  }

  int l  = tid & 31;
  int kp = tid >> 5;                 // warp id: owns k-eighth [32kp, 32kp+32)
  int pr = tid >> 6;                 // update phase (tid<128): 0/1 -> j=2c+pr
  int ub = tid & 63;                 // update phase: batch
  float c = 0.f;
  __syncthreads();

  const ulonglong2* wq2 = (const ulonglong2*)Wq;   // [256][4]
  const int* myflag = &g_flag[0];
  int fidx = (kp*16 + (l & 15))*FSTR;              // producer flag (lanes 0-15)
  const unsigned long long* hbase = (const unsigned long long*)(&g_hT[0][0][0]);
  int kbase = kp*32;

  for (int s = 0; s < S_; s++) {
    int par = s & 1;
    // prefetch xg gate inputs (independent of h)
    float xgi=0.f, xgf=0.f, xgg=0.f, xgo=0.f;
    if (tid < 128) {
      size_t base = ((size_t)s*G4_ + 2*cta + pr)*B_ + ub;
      xgi = __ldg(&g_xgT[base]);
      xgf = __ldg(&g_xgT[base + (size_t)256*B_]);
      xgg = __ldg(&g_xgT[base + (size_t)512*B_]);
      xgo = __ldg(&g_xgT[base + (size_t)768*B_]);
    }

    // wait for this warp's 16 producer CTAs to have published h(s-1)
    if (l < 16) {
      const int* fp = myflag + fidx;
      while (ld_acquire(fp) < s) { }
    }
    __syncwarp();

    // gate GEMV on this warp's k-eighth, h straight from L2
    const unsigned long long* hp = hbase + (size_t)par*(H_*B_/2) + l;
    unsigned long long acc0=0ULL, acc1=0ULL, acc2=0ULL, acc3=0ULL;
    unsigned long long acc4=0ULL, acc5=0ULL, acc6=0ULL, acc7=0ULL;
    #pragma unroll 8
    for (int k = kbase; k < kbase + 32; k++) {
      unsigned long long h2 = __ldcg(hp + (size_t)k*32);
      ulonglong2 w01 = wq2[k*4 + 0];
      ulonglong2 w23 = wq2[k*4 + 1];
      ulonglong2 w45 = wq2[k*4 + 2];
      ulonglong2 w67 = wq2[k*4 + 3];
      fma2(acc0, w01.x, h2); fma2(acc1, w01.y, h2);
      fma2(acc2, w23.x, h2); fma2(acc3, w23.y, h2);
      fma2(acc4, w45.x, h2); fma2(acc5, w45.y, h2);
      fma2(acc6, w67.x, h2); fma2(acc7, w67.y, h2);
    }
    {
      unsigned long long* pp = ((unsigned long long*)psum) + kp*8*32 + l;
      pp[0*32] = acc0; pp[1*32] = acc1; pp[2*32] = acc2; pp[3*32] = acc3;
      pp[4*32] = acc4; pp[5*32] = acc5; pp[6*32] = acc6; pp[7*32] = acc7;
    }
    __syncthreads();

    // cell update for j = 2c + pr, batch ub (8-part k reduction)
    if (tid < 128) {
      float pre[4];
      #pragma unroll
      for (int g = 0; g < 4; g++) {
        int r = g*2 + pr;
        float sum = 0.f;
        #pragma unroll
        for (int kq = 0; kq < 8; kq++)
          sum += psum[(kq*8 + r)*64 + ub];
        pre[g] = sum;
      }
      pre[0] += xgi; pre[1] += xgf; pre[2] += xgg; pre[3] += xgo;
      c = sigmf(pre[1])*c + sigmf(pre[0])*tanhf(pre[2]);
      float h = sigmf(pre[3])*tanhf(c);
      int j = 2*cta + pr;
      g_houtT[((size_t)s*H_ + j)*B_ + ub] = h;   // coalesced 256B rows
      g_hT[1-par][j][ub] = h;
    }
    __syncthreads();                 // order all h-writes before the release
    if (tid == 0) st_release(&g_flag[cta*FSTR], s + 1);
  }
}

// ---------------- K3b: transpose houtT (s,h,b) -> hout (b,s,h) ---------------
__global__ __launch_bounds__(256) void hout_transpose_kernel() {
  __shared__ float tile[64][65];
  int j0 = blockIdx.x*64;
  int s  = blockIdx.y;
  int t  = threadIdx.x;
  int b  = t & 63, jr = t >> 6;
  for (int jj = 0; jj < 64; jj += 4) {
    int j = jj + jr;
    tile[j][b] = g_houtT[((size_t)s*H_ + j0 + j)*B_ + b];
  }
  __syncthreads();
  int j = t & 63, bg = t >> 6;
  for (int bb = 0; bb < 64; bb += 4) {
    int bq = bb + bg;
    g_hout[((size_t)bq*S_ + s)*H_ + j0 + j] = tile[j][bq];
  }
}

// ---------------- K4: masked attention pooling + logits ----------------------
__global__ __launch_bounds__(256) void attend_kernel(
    const int*   __restrict__ lengths,
    const float* __restrict__ attn_w,
    const float* __restrict__ attn_b,
    const float* __restrict__ out_w,
    const float* __restrict__ out_b,
    float*       __restrict__ out) {
  __shared__ float sw[H_];
  __shared__ float sc[S_];
  __shared__ float smax, sinv;
  __shared__ float lg[3];
  int tid = threadIdx.x;
  int b = blockIdx.x;
  const float* ho = g_hout + (size_t)b*S_*H_;

  sw[tid] = attn_w[tid];
  if (tid < 3) lg[tid] = 0.f;
  __syncthreads();

  int lane = tid & 31, wid = tid >> 5;  // 8 warps
  float ab = attn_b[0];
  for (int s = wid; s < S_; s += 8) {
    float p = 0.f;
    for (int k = lane; k < H_; k += 32) p += ho[(size_t)s*H_ + k]*sw[k];
    #pragma unroll
    for (int off = 16; off; off >>= 1) p += __shfl_down_sync(0xffffffffu, p, off);
    if (lane == 0) sc[s] = p + ab;
  }
  __syncthreads();

  int len = lengths[b];
  if (tid == 0) {
    float m = -1e30f;
    for (int s = 0; s < len; s++) m = fmaxf(m, sc[s]);
    smax = m;
  }
  __syncthreads();
  if (tid < S_) sc[tid] = (tid < len) ? expf(sc[tid]-smax) : 0.f;
  __syncthreads();
  if (tid == 0) {
    float sum = 0.f;
    for (int s = 0; s < S_; s++) sum += sc[s];
    sinv = 1.f/sum;
  }
  __syncthreads();

  float att = 0.f;
  for (int s = 0; s < S_; s++) att += sc[s]*ho[(size_t)s*H_ + tid];
  att *= sinv;
  #pragma unroll
  for (int c = 0; c < 3; c++) atomicAdd(&lg[c], att*out_w[c*H_ + tid]);
  __syncthreads();
  if (tid < 3) out[b*3 + tid] = lg[tid] + out_b[tid];
}

// ---------------- launcher ---------------------------------------------------
extern "C" void kernel_launch(void* const* d_in, const int* in_sizes, int n_in,
                              void* d_out, int out_size) {
  const int*   inputs  = (const int*)  d_in[0];
  // d_in[1] = context (unused by the reference)
  const int*   triples = (const int*)  d_in[2];
  const int*   lengths = (const int*)  d_in[3];
  const int*   id2     = (const int*)  d_in[4];
  const float* emb     = (const float*)d_in[5];
  const float* ent     = (const float*)d_in[6];
  const float* rel     = (const float*)d_in[7];
  const float* W_ent   = (const float*)d_in[8];
  const float* W_ih    = (const float*)d_in[9];
  const float* W_hh    = (const float*)d_in[10];
  const float* b_lstm  = (const float*)d_in[11];
  const float* attn_w  = (const float*)d_in[12];
  const float* attn_b  = (const float*)d_in[13];
  const float* out_w   = (const float*)d_in[14];
  const float* out_b   = (const float*)d_in[15];
  float* out = (float*)d_out;

  prep_kernel<<<(KP_*G4_+255)/256, 256>>>(W_ih);

  size_t sm1 = (size_t)(200*WTS + T_*200 + T_*D_) * sizeof(float);  // ~92.8 KB
  cudaFuncSetAttribute(graph_tin_kernel,
                       cudaFuncAttributeMaxDynamicSharedMemorySize, (int)sm1);
  graph_tin_kernel<<<NTOK/TOKB, 256, sm1>>>(inputs, triples, id2,
                                            emb, ent, rel, W_ent);

  dim3 g2(G4_/BN, NTOK/BM);
  gemm_xg_kernel<<<g2, 256>>>(b_lstm);

  xg_transpose_kernel<<<dim3(G4_/64, S_), 256>>>();

  lstm5_kernel<<<NCTA, 256>>>(W_hh);

  hout_transpose_kernel<<<dim3(H_/64, S_), 256>>>();

  attend_kernel<<<B_, 256>>>(lengths, attn_w, attn_b, out_w, out_b, out);
}